// round 4
// baseline (speedup 1.0000x reference)
#include <cuda_runtime.h>
#include <cuda_bf16.h>
#include <cstdint>
#include <cmath>

// Problem constants
#define LQ    512   // sequence length
#define BQ    64    // batch
#define DQ    512   // input dim
#define HALFQ 256   // hidden per direction
#define GATES 1024  // 4*HALF

// ---------------------------------------------------------------------------
// Scratch: precomputed input projections (+ folded biases), permuted layout:
//   xw[dir][t][bg][slice][bl][gate*32+j]
//   dir:2, t:512, bg:8 (batch group), slice:8 (cluster rank), bl:8, 128 gates
// = 2*512*8*8*8*128 floats = 256 MiB
// ---------------------------------------------------------------------------
__device__ __align__(16) float g_xw[2ull * 512 * 8 * 8 * 8 * 128];

// ===========================================================================
// Kernel 1: fp32 GEMM  C[32768, 2048] = x[32768,512] @ Wcat^T + (b_ih + b_hh)
// writes into g_xw permuted layout. 128x128 tile, BK=16, 256 thr, 8x8 microtile
// ===========================================================================
#define BM 128
#define BN 128
#define BK 16
#define SPITCH 132

__global__ __launch_bounds__(256, 2)
void lstm_input_gemm(const float* __restrict__ x,
                     const float* __restrict__ Wf,
                     const float* __restrict__ Wb,
                     const float* __restrict__ bihf,
                     const float* __restrict__ bhhf,
                     const float* __restrict__ bihb,
                     const float* __restrict__ bhhb)
{
    __shared__ float As[BK][SPITCH];
    __shared__ float Bs[BK][SPITCH];

    const int tid = threadIdx.x;
    const int tx = tid & 15;       // 0..15
    const int ty = tid >> 4;       // 0..15
    const int m0 = blockIdx.x * BM;
    const int n0 = blockIdx.y * BN;

    const int lr = tid >> 2;           // 0..63
    const int lc = (tid & 3) * 4;      // 0,4,8,12

    float acc[8][8];
#pragma unroll
    for (int i = 0; i < 8; i++)
#pragma unroll
        for (int j = 0; j < 8; j++) acc[i][j] = 0.f;

    for (int k0 = 0; k0 < DQ; k0 += BK) {
        // ---- global loads (registers) ----
        float4 a0 = *(const float4*)&x[(size_t)(m0 + lr) * DQ + k0 + lc];
        float4 a1 = *(const float4*)&x[(size_t)(m0 + lr + 64) * DQ + k0 + lc];

        int n_a = n0 + lr;
        int n_b = n0 + lr + 64;
        const float* pA = (n_a < GATES) ? Wf : Wb;
        const float* pB = (n_b < GATES) ? Wf : Wb;
        float4 b0 = *(const float4*)&pA[(size_t)(n_a & (GATES - 1)) * DQ + k0 + lc];
        float4 b1 = *(const float4*)&pB[(size_t)(n_b & (GATES - 1)) * DQ + k0 + lc];

        __syncthreads();   // previous tile fully consumed
        As[lc + 0][lr] = a0.x; As[lc + 1][lr] = a0.y;
        As[lc + 2][lr] = a0.z; As[lc + 3][lr] = a0.w;
        As[lc + 0][lr + 64] = a1.x; As[lc + 1][lr + 64] = a1.y;
        As[lc + 2][lr + 64] = a1.z; As[lc + 3][lr + 64] = a1.w;
        Bs[lc + 0][lr] = b0.x; Bs[lc + 1][lr] = b0.y;
        Bs[lc + 2][lr] = b0.z; Bs[lc + 3][lr] = b0.w;
        Bs[lc + 0][lr + 64] = b1.x; Bs[lc + 1][lr + 64] = b1.y;
        Bs[lc + 2][lr + 64] = b1.z; Bs[lc + 3][lr + 64] = b1.w;
        __syncthreads();

#pragma unroll
        for (int kk = 0; kk < BK; ++kk) {
            float a[8], b[8];
            *(float4*)&a[0] = *(const float4*)&As[kk][ty * 8];
            *(float4*)&a[4] = *(const float4*)&As[kk][ty * 8 + 4];
            *(float4*)&b[0] = *(const float4*)&Bs[kk][tx * 8];
            *(float4*)&b[4] = *(const float4*)&Bs[kk][tx * 8 + 4];
#pragma unroll
            for (int i = 0; i < 8; i++)
#pragma unroll
                for (int j = 0; j < 8; j++)
                    acc[i][j] += a[i] * b[j];
        }
    }

    // ---- epilogue: add biases, scatter to permuted layout ----
    // n block: all 8 n's of this thread share dir/gate/slice (runs of 8 within
    // a 32-run, 128-aligned tiles never straddle boundaries)
    const int n_base = n0 + tx * 8;
    const int dir   = n_base >> 10;
    const int row   = n_base & (GATES - 1);
    const int gate  = row >> 8;
    const int slice = (row >> 5) & 7;
    const int j0    = row & 31;

    const float* bi = dir ? bihb : bihf;
    const float* bh = dir ? bhhb : bhhf;
    float biasv[8];
#pragma unroll
    for (int jj = 0; jj < 8; jj++)
        biasv[jj] = bi[row + jj] + bh[row + jj];

#pragma unroll
    for (int i = 0; i < 8; i++) {
        int m  = m0 + ty * 8 + i;
        int t  = m >> 6;
        int b  = m & 63;
        int bg = b >> 3;
        int bl = b & 7;
        size_t base = (((((size_t)dir * LQ + t) * 8 + bg) * 8 + slice) * 8 + bl) * 128
                      + gate * 32 + j0;
        float4 v0 = make_float4(acc[i][0] + biasv[0], acc[i][1] + biasv[1],
                                acc[i][2] + biasv[2], acc[i][3] + biasv[3]);
        float4 v1 = make_float4(acc[i][4] + biasv[4], acc[i][5] + biasv[5],
                                acc[i][6] + biasv[6], acc[i][7] + biasv[7]);
        *(float4*)&g_xw[base]     = v0;
        *(float4*)&g_xw[base + 4] = v1;
    }
}

// ===========================================================================
// Kernel 2: recurrence. Cluster of 8 CTAs handles (dir, batch-group of 8).
// Each CTA owns the i/f/g/o gate rows of 32 h-indices (W slice 128x256 fp32
// in smem, transposed, pitch 129 -> conflict-free). h double-buffered in smem,
// broadcast to peers via DSMEM each step; one cluster arrive/wait per step.
// ===========================================================================
#define REC_SMEM_FLOATS (256 * 129 /*Wt*/ + 2 * 8 * 256 /*h dbl*/ + 8 * 128 /*gates*/)

__device__ __forceinline__ uint32_t smem_u32(const void* p) {
    uint32_t a;
    asm("{ .reg .u64 t; cvta.to.shared.u64 t, %1; cvt.u32.u64 %0, t; }"
        : "=r"(a) : "l"(p));
    return a;
}
__device__ __forceinline__ uint32_t ctarank() {
    uint32_t r;
    asm("mov.u32 %0, %%cluster_ctarank;" : "=r"(r));
    return r;
}

__global__ void __cluster_dims__(8, 1, 1) __launch_bounds__(256, 1)
lstm_recurrence(const float* __restrict__ Whh_f,
                const float* __restrict__ Whh_b,
                const float* __restrict__ mask,
                float* __restrict__ out)
{
    extern __shared__ float sm[];
    float* Wt    = sm;                       // [256][129]  (k-major, padded)
    float* hbuf  = sm + 256 * 129;           // [2][8][256]
    float* gt    = hbuf + 2 * 8 * 256;       // [8][128]

    const int tid = threadIdx.x;
    const uint32_t s = ctarank();            // cluster rank = h-slice
    const int gid = blockIdx.x >> 3;         // 0..15
    const int dir = gid >> 3;                // 0 fwd, 1 bwd
    const int bg  = gid & 7;                 // batch group (8 batches)

    const float* Whh = dir ? Whh_b : Whh_f;

    // Load weight slice, transposed: local row r = gate*32+j maps to global
    // W_hh row gate*256 + s*32 + j. Wt[k*129 + r].
    for (int idx = tid; idx < 128 * 256; idx += 256) {
        int r = idx >> 8;
        int k = idx & 255;
        int grow = ((r >> 5) << 8) | ((int)s << 5) | (r & 31);
        Wt[k * 129 + r] = Whh[(size_t)grow * 256 + k];
    }
    // zero both h buffers
    for (int idx = tid; idx < 2 * 8 * 256; idx += 256) hbuf[idx] = 0.f;
    __syncthreads();

    // matvec role: row r (0..127), batches half*4..half*4+3
    const int r    = tid & 127;
    const int half = tid >> 7;
    // activation role: one (batch, j) per thread
    const int ab = tid >> 5;   // 0..7
    const int aj = tid & 31;   // 0..31
    const int bglob_a = bg * 8 + ab;

    float c = 0.f;

    for (int step = 0; step < LQ; step++) {
        const int t = dir ? (LQ - 1 - step) : step;
        const int p = step & 1;

        // ---- prefetch (independent of h) BEFORE the cluster wait ----
        const float* xwp = g_xw + (((((size_t)dir * LQ + t) * 8 + bg) * 8 + s) * 1024);
        float a0 = xwp[(half * 4 + 0) * 128 + r];
        float a1 = xwp[(half * 4 + 1) * 128 + r];
        float a2 = xwp[(half * 4 + 2) * 128 + r];
        float a3 = xwp[(half * 4 + 3) * 128 + r];
        float m  = __ldg(&mask[t * BQ + bglob_a]);

        if (step > 0)
            asm volatile("barrier.cluster.wait.aligned;" ::: "memory");

        // ---- matvec: gates += h @ Whh^T (slice) ----
        const float* h = hbuf + p * 2048 + (half * 4) * 256;
#pragma unroll 8
        for (int k = 0; k < 256; k += 4) {
            float w0 = Wt[(k + 0) * 129 + r];
            float w1 = Wt[(k + 1) * 129 + r];
            float w2 = Wt[(k + 2) * 129 + r];
            float w3 = Wt[(k + 3) * 129 + r];
            float4 h0 = *(const float4*)(h + 0 * 256 + k);
            float4 h1 = *(const float4*)(h + 1 * 256 + k);
            float4 h2 = *(const float4*)(h + 2 * 256 + k);
            float4 h3 = *(const float4*)(h + 3 * 256 + k);
            a0 += w0 * h0.x + w1 * h0.y + w2 * h0.z + w3 * h0.w;
            a1 += w0 * h1.x + w1 * h1.y + w2 * h1.z + w3 * h1.w;
            a2 += w0 * h2.x + w1 * h2.y + w2 * h2.z + w3 * h2.w;
            a3 += w0 * h3.x + w1 * h3.y + w2 * h3.z + w3 * h3.w;
        }
        gt[(half * 4 + 0) * 128 + r] = a0;
        gt[(half * 4 + 1) * 128 + r] = a1;
        gt[(half * 4 + 2) * 128 + r] = a2;
        gt[(half * 4 + 3) * 128 + r] = a3;
        __syncthreads();

        // ---- activations: one (batch, h-index) per thread ----
        float gi = gt[ab * 128 +       aj];
        float gf = gt[ab * 128 +  32 + aj];
        float gg = gt[ab * 128 +  64 + aj];
        float go = gt[ab * 128 +  96 + aj];
        float i_ = 1.f / (1.f + __expf(-gi));
        float f_ = 1.f / (1.f + __expf(-gf));
        float g_ = tanhf(gg);
        float o_ = 1.f / (1.f + __expf(-go));
        c = f_ * c + i_ * g_;
        float hv = o_ * tanhf(c);
        hv *= m;
        c  *= m;

        // output: out[t][b][dir*256 + s*32 + j]
        out[((size_t)t * BQ + bglob_a) * (2 * HALFQ) + dir * HALFQ + s * 32 + aj] = hv;

        if (step < LQ - 1) {
            // broadcast h slice to all 8 CTAs' next-phase h buffer
            float* dst = hbuf + (p ^ 1) * 2048 + ab * 256 + (int)s * 32 + aj;
            uint32_t la = smem_u32(dst);
#pragma unroll
            for (int rk = 0; rk < 8; rk++) {
                uint32_t ra;
                asm volatile("mapa.shared::cluster.u32 %0, %1, %2;"
                             : "=r"(ra) : "r"(la), "r"(rk));
                asm volatile("st.shared::cluster.f32 [%0], %1;"
                             :: "r"(ra), "f"(hv) : "memory");
            }
            asm volatile("barrier.cluster.arrive.aligned;" ::: "memory");
        }
    }
}

// ===========================================================================
// Launch
// Inputs (metadata order): x, mask, W_ih_f, W_hh_f, b_ih_f, b_hh_f,
//                          W_ih_b, W_hh_b, b_ih_b, b_hh_b
// Output: float32 (L, B, 2*HALF)
// ===========================================================================
extern "C" void kernel_launch(void* const* d_in, const int* in_sizes, int n_in,
                              void* d_out, int out_size)
{
    const float* x     = (const float*)d_in[0];
    const float* mask  = (const float*)d_in[1];
    const float* Wihf  = (const float*)d_in[2];
    const float* Whhf  = (const float*)d_in[3];
    const float* bihf  = (const float*)d_in[4];
    const float* bhhf  = (const float*)d_in[5];
    const float* Wihb  = (const float*)d_in[6];
    const float* Whhb  = (const float*)d_in[7];
    const float* bihb  = (const float*)d_in[8];
    const float* bhhb  = (const float*)d_in[9];
    float* out = (float*)d_out;

    // Phase 1: input projection GEMM into permuted scratch
    dim3 ggrid(32768 / BM, 2048 / BN);
    lstm_input_gemm<<<ggrid, 256>>>(x, Wihf, Wihb, bihf, bhhf, bihb, bhhb);

    // Phase 2: recurrence (128 CTAs, clusters of 8)
    const int rec_smem = REC_SMEM_FLOATS * (int)sizeof(float);
    cudaFuncSetAttribute(lstm_recurrence,
                         cudaFuncAttributeMaxDynamicSharedMemorySize, rec_smem);
    lstm_recurrence<<<128, 256, rec_smem>>>(Whhf, Whhb, mask, out);
}

// round 8
// speedup vs baseline: 1.0845x; 1.0845x over previous
#include <cuda_runtime.h>
#include <cuda_bf16.h>
#include <cstdint>
#include <cmath>

// Problem constants
#define LQ    512   // sequence length
#define BQ    64    // batch
#define DQ    512   // input dim
#define HALFQ 256   // hidden per direction
#define GATES 1024  // 4*HALF

// ---------------------------------------------------------------------------
// Scratch
// g_xw: precomputed input projections (+ folded biases), permuted layout:
//   xw[dir][t][bg][slice][bl][gate*32+j]   (2*512*8*8*8*128 floats = 256 MiB)
// g_xhi/g_xlo: split-bf16 x        [32768][512]
// g_whi/g_wlo: split-bf16 Wcat     [2048][512]  (rows 0..1023 = fwd, rest bwd)
// g_bsum: b_ih + b_hh per gate row [2048]
// ---------------------------------------------------------------------------
__device__ __align__(16) float         g_xw[2ull * 512 * 8 * 8 * 8 * 128];
__device__ __align__(16) __nv_bfloat16 g_xhi[32768ull * 512];
__device__ __align__(16) __nv_bfloat16 g_xlo[32768ull * 512];
__device__ __align__(16) __nv_bfloat16 g_whi[2048ull * 512];
__device__ __align__(16) __nv_bfloat16 g_wlo[2048ull * 512];
__device__ __align__(16) float         g_bsum[2048];

// ---------------------------------------------------------------------------
// Helpers
// ---------------------------------------------------------------------------
__device__ __forceinline__ uint32_t smem_u32(const void* p) {
    uint32_t a;
    asm("{ .reg .u64 t; cvta.to.shared.u64 t, %1; cvt.u32.u64 %0, t; }"
        : "=r"(a) : "l"(p));
    return a;
}
__device__ __forceinline__ uint32_t ctarank() {
    uint32_t r;
    asm("mov.u32 %0, %%cluster_ctarank;" : "=r"(r));
    return r;
}
__device__ __forceinline__ void cp16(uint32_t dst, const void* src) {
    asm volatile("cp.async.cg.shared.global [%0], [%1], 16;"
                 :: "r"(dst), "l"(src) : "memory");
}
__device__ __forceinline__ void cp_commit() {
    asm volatile("cp.async.commit_group;" ::: "memory");
}
template <int N>
__device__ __forceinline__ void cp_wait() {
    asm volatile("cp.async.wait_group %0;" :: "n"(N) : "memory");
}
__device__ __forceinline__ void ldm_x4(uint32_t& r0, uint32_t& r1,
                                       uint32_t& r2, uint32_t& r3, uint32_t a) {
    asm volatile("ldmatrix.sync.aligned.m8n8.x4.shared.b16 {%0,%1,%2,%3}, [%4];"
                 : "=r"(r0), "=r"(r1), "=r"(r2), "=r"(r3) : "r"(a));
}
__device__ __forceinline__ void mma_bf16(float* c, const uint32_t* a,
                                         uint32_t b0, uint32_t b1) {
    asm volatile("mma.sync.aligned.m16n8k16.row.col.f32.bf16.bf16.f32 "
                 "{%0,%1,%2,%3}, {%4,%5,%6,%7}, {%8,%9}, {%0,%1,%2,%3};"
                 : "+f"(c[0]), "+f"(c[1]), "+f"(c[2]), "+f"(c[3])
                 : "r"(a[0]), "r"(a[1]), "r"(a[2]), "r"(a[3]),
                   "r"(b0), "r"(b1));
}

// ===========================================================================
// Kernel 0a: split x into hi/lo bf16
// ===========================================================================
__global__ __launch_bounds__(256)
void conv_x(const float* __restrict__ x)
{
    size_t i = ((size_t)blockIdx.x * 256 + threadIdx.x) * 4;
    float4 v = *(const float4*)(x + i);
    float vv[4] = {v.x, v.y, v.z, v.w};
    unsigned short hi[4], lo[4];
#pragma unroll
    for (int j = 0; j < 4; j++) {
        __nv_bfloat16 h = __float2bfloat16(vv[j]);
        __nv_bfloat16 l = __float2bfloat16(vv[j] - __bfloat162float(h));
        hi[j] = __bfloat16_as_ushort(h);
        lo[j] = __bfloat16_as_ushort(l);
    }
    *(uint2*)((unsigned short*)g_xhi + i) = *(uint2*)hi;
    *(uint2*)((unsigned short*)g_xlo + i) = *(uint2*)lo;
}

// ===========================================================================
// Kernel 0b: split W into hi/lo bf16 (concat fwd|bwd), and combined biases
// ===========================================================================
__global__ __launch_bounds__(256)
void conv_w(const float* __restrict__ Wf, const float* __restrict__ Wb,
            const float* __restrict__ bihf, const float* __restrict__ bhhf,
            const float* __restrict__ bihb, const float* __restrict__ bhhb)
{
    size_t e0 = ((size_t)blockIdx.x * 256 + threadIdx.x) * 4;
    int row = (int)(e0 >> 9);
    int col = (int)(e0 & 511);
    const float* src = (row < GATES) ? (Wf + (size_t)row * 512 + col)
                                     : (Wb + (size_t)(row - GATES) * 512 + col);
    float4 v = *(const float4*)src;
    float vv[4] = {v.x, v.y, v.z, v.w};
    unsigned short hi[4], lo[4];
#pragma unroll
    for (int j = 0; j < 4; j++) {
        __nv_bfloat16 h = __float2bfloat16(vv[j]);
        __nv_bfloat16 l = __float2bfloat16(vv[j] - __bfloat162float(h));
        hi[j] = __bfloat16_as_ushort(h);
        lo[j] = __bfloat16_as_ushort(l);
    }
    *(uint2*)((unsigned short*)g_whi + e0) = *(uint2*)hi;
    *(uint2*)((unsigned short*)g_wlo + e0) = *(uint2*)lo;

    if (blockIdx.x == 0) {
        for (int n = threadIdx.x; n < 2048; n += 256) {
            int r = n & (GATES - 1);
            g_bsum[n] = (n < GATES) ? (bihf[r] + bhhf[r]) : (bihb[r] + bhhb[r]);
        }
    }
}

// ===========================================================================
// Kernel 1: mma.sync bf16 GEMM  C[32768,2048] = x @ Wcat^T + bsum
// split-bf16 3-pass (hi*hi + hi*lo + lo*hi), fp32 accumulate.
// 128x128 tile, BK=32, 3-stage cp.async pipeline, 8 warps (warp tile 32x64).
// Smem rows padded to 40 halves (80B) -> conflict-free ldmatrix.
// Epilogue scatters into permuted g_xw.
// ===========================================================================
#define STG_HALF 20480                      // halves per stage (4 * 128*40)
#define GEMM_SMEM (3 * STG_HALF * 2)        // 122880 bytes

// issue cp.async for one stage: 4 matrices x 128 rows x 4 x 16B.
// mat is a compile-time unroll index so the src pointer stays in registers.
__device__ __forceinline__ void stage_load(uint32_t smbase, int st,
                                           int m0, int n0, int k0, int tid)
{
    const __nv_bfloat16* const xh = g_xhi + (size_t)m0 * 512 + k0;
    const __nv_bfloat16* const xl = g_xlo + (size_t)m0 * 512 + k0;
    const __nv_bfloat16* const wh = g_whi + (size_t)n0 * 512 + k0;
    const __nv_bfloat16* const wl = g_wlo + (size_t)n0 * 512 + k0;
    const uint32_t sbase = smbase + st * (STG_HALF * 2);
    const int r0  = tid >> 2;          // 0..63
    const int seg = tid & 3;           // 0..3

#pragma unroll
    for (int mat = 0; mat < 4; mat++) {
        const __nv_bfloat16* src =
            (mat == 0) ? xh : (mat == 1) ? xl : (mat == 2) ? wh : wl;
#pragma unroll
        for (int hh = 0; hh < 2; hh++) {
            int row = r0 + hh * 64;
            uint32_t dst = sbase + (uint32_t)(mat * 10240 + row * 80 + seg * 16);
            cp16(dst, src + (size_t)row * 512 + seg * 8);
        }
    }
}

__global__ __launch_bounds__(256)
void lstm_gemm_mma()
{
    extern __shared__ char smg[];
    const uint32_t smbase = smem_u32(smg);
    const int tid  = threadIdx.x;
    const int lane = tid & 31;
    const int wid  = tid >> 5;
    const int wm = (wid & 3) * 32;          // warp m offset
    const int wn = (wid >> 2) * 64;         // warp n offset
    const int n0 = blockIdx.x * 128;        // 16 n-tiles (fast -> x reuse in L2)
    const int m0 = blockIdx.y * 128;        // 256 m-tiles

    float acc[2][8][4];
#pragma unroll
    for (int i = 0; i < 2; i++)
#pragma unroll
        for (int j = 0; j < 8; j++)
#pragma unroll
            for (int q = 0; q < 4; q++) acc[i][j][q] = 0.f;

    // ldmatrix address offsets within a stage
    // A: rows (lane&15), col-half (lane>>4)
    const uint32_t a_row = (uint32_t)(lane & 15);
    const uint32_t a_col = (uint32_t)((lane >> 4) * 8);
    // B: rows (lane&7)+((lane>>4)<<3), col-half ((lane>>3)&1)
    const uint32_t b_row = (uint32_t)((lane & 7) + ((lane >> 4) << 3));
    const uint32_t b_col = (uint32_t)(((lane >> 3) & 1) * 8);

    // prologue: stages 0,1
    stage_load(smbase, 0, m0, n0, 0, tid);  cp_commit();
    stage_load(smbase, 1, m0, n0, 32, tid); cp_commit();

    for (int c = 0; c < 16; c++) {
        if (c + 2 < 16) stage_load(smbase, (c + 2) % 3, m0, n0, (c + 2) * 32, tid);
        cp_commit();
        cp_wait<2>();
        __syncthreads();

        uint32_t sb  = smbase + (uint32_t)((c % 3) * (STG_HALF * 2));
        uint32_t sAh = sb;
        uint32_t sAl = sb + 10240;
        uint32_t sBh = sb + 20480;
        uint32_t sBl = sb + 30720;

#pragma unroll
        for (int kk = 0; kk < 2; kk++) {
            const uint32_t kb = (uint32_t)(kk * 32);  // 16 halves = 32 bytes

            uint32_t ah[2][4], al[2][4];
#pragma unroll
            for (int tm = 0; tm < 2; tm++) {
                uint32_t roff = (uint32_t)(wm + tm * 16) + a_row;
                uint32_t off = roff * 80 + kb + a_col * 2;
                ldm_x4(ah[tm][0], ah[tm][1], ah[tm][2], ah[tm][3], sAh + off);
                ldm_x4(al[tm][0], al[tm][1], al[tm][2], al[tm][3], sAl + off);
            }

            uint32_t b[16];
#pragma unroll
            for (int p = 0; p < 4; p++) {
                uint32_t roff = (uint32_t)(wn + p * 16) + b_row;
                uint32_t off = roff * 80 + kb + b_col * 2;
                ldm_x4(b[p * 4 + 0], b[p * 4 + 1], b[p * 4 + 2], b[p * 4 + 3],
                       sBh + off);
            }
            // hi*hi and lo*hi
#pragma unroll
            for (int tm = 0; tm < 2; tm++)
#pragma unroll
                for (int tn = 0; tn < 8; tn++) {
                    mma_bf16(acc[tm][tn], ah[tm], b[tn * 2], b[tn * 2 + 1]);
                    mma_bf16(acc[tm][tn], al[tm], b[tn * 2], b[tn * 2 + 1]);
                }
            // hi*lo
#pragma unroll
            for (int p = 0; p < 4; p++) {
                uint32_t roff = (uint32_t)(wn + p * 16) + b_row;
                uint32_t off = roff * 80 + kb + b_col * 2;
                ldm_x4(b[p * 4 + 0], b[p * 4 + 1], b[p * 4 + 2], b[p * 4 + 3],
                       sBl + off);
            }
#pragma unroll
            for (int tm = 0; tm < 2; tm++)
#pragma unroll
                for (int tn = 0; tn < 8; tn++)
                    mma_bf16(acc[tm][tn], ah[tm], b[tn * 2], b[tn * 2 + 1]);
        }
        __syncthreads();
    }

    // ---- epilogue: add bias, scatter acc into permuted g_xw ----
    // acc tile (tm,tn): rows m0+wm+tm*16+(lane>>2)+{0,8},
    //                   cols n0+wn+tn*8+(lane&3)*2+{0,1}
#pragma unroll
    for (int tm = 0; tm < 2; tm++) {
#pragma unroll
        for (int tn = 0; tn < 8; tn++) {
            const int n    = n0 + wn + tn * 8 + (lane & 3) * 2;
            const int dir  = n >> 10;
            const int rowg = n & (GATES - 1);
            const int gate = rowg >> 8;
            const int slc  = (rowg >> 5) & 7;
            const int j    = rowg & 31;
            float b0 = g_bsum[n];
            float b1 = g_bsum[n + 1];
#pragma unroll
            for (int rr = 0; rr < 2; rr++) {
                const int m  = m0 + wm + tm * 16 + (lane >> 2) + rr * 8;
                const int t  = m >> 6;
                const int bq = m & 63;
                size_t base = (((((size_t)dir * LQ + t) * 8 + (bq >> 3)) * 8 + slc) * 8
                               + (bq & 7)) * 128 + gate * 32 + j;
                float2 v;
                v.x = acc[tm][tn][rr * 2 + 0] + b0;
                v.y = acc[tm][tn][rr * 2 + 1] + b1;
                *(float2*)&g_xw[base] = v;
            }
        }
    }
}

// ===========================================================================
// Kernel 2: recurrence (unchanged — passing since R3). Cluster of 8 CTAs per
// (dir, batch-group of 8). W slice 128x256 fp32 transposed in smem; h double-
// buffered, broadcast via DSMEM each step; one cluster arrive/wait per step.
// ===========================================================================
#define REC_SMEM_FLOATS (256 * 129 /*Wt*/ + 2 * 8 * 256 /*h dbl*/ + 8 * 128 /*gates*/)

__global__ void __cluster_dims__(8, 1, 1) __launch_bounds__(256, 1)
lstm_recurrence(const float* __restrict__ Whh_f,
                const float* __restrict__ Whh_b,
                const float* __restrict__ mask,
                float* __restrict__ out)
{
    extern __shared__ float sm[];
    float* Wt    = sm;                       // [256][129]  (k-major, padded)
    float* hbuf  = sm + 256 * 129;           // [2][8][256]
    float* gt    = hbuf + 2 * 8 * 256;       // [8][128]

    const int tid = threadIdx.x;
    const uint32_t s = ctarank();            // cluster rank = h-slice
    const int gid = blockIdx.x >> 3;         // 0..15
    const int dir = gid >> 3;                // 0 fwd, 1 bwd
    const int bg  = gid & 7;                 // batch group (8 batches)

    const float* Whh = dir ? Whh_b : Whh_f;

    for (int idx = tid; idx < 128 * 256; idx += 256) {
        int r = idx >> 8;
        int k = idx & 255;
        int grow = ((r >> 5) << 8) | ((int)s << 5) | (r & 31);
        Wt[k * 129 + r] = Whh[(size_t)grow * 256 + k];
    }
    for (int idx = tid; idx < 2 * 8 * 256; idx += 256) hbuf[idx] = 0.f;
    __syncthreads();

    const int r    = tid & 127;
    const int half = tid >> 7;
    const int ab = tid >> 5;   // 0..7
    const int aj = tid & 31;   // 0..31
    const int bglob_a = bg * 8 + ab;

    float c = 0.f;

    for (int step = 0; step < LQ; step++) {
        const int t = dir ? (LQ - 1 - step) : step;
        const int p = step & 1;

        const float* xwp = g_xw + (((((size_t)dir * LQ + t) * 8 + bg) * 8 + s) * 1024);
        float a0 = xwp[(half * 4 + 0) * 128 + r];
        float a1 = xwp[(half * 4 + 1) * 128 + r];
        float a2 = xwp[(half * 4 + 2) * 128 + r];
        float a3 = xwp[(half * 4 + 3) * 128 + r];
        float m  = __ldg(&mask[t * BQ + bglob_a]);

        if (step > 0)
            asm volatile("barrier.cluster.wait.aligned;" ::: "memory");

        const float* h = hbuf + p * 2048 + (half * 4) * 256;
#pragma unroll 8
        for (int k = 0; k < 256; k += 4) {
            float w0 = Wt[(k + 0) * 129 + r];
            float w1 = Wt[(k + 1) * 129 + r];
            float w2 = Wt[(k + 2) * 129 + r];
            float w3 = Wt[(k + 3) * 129 + r];
            float4 h0 = *(const float4*)(h + 0 * 256 + k);
            float4 h1 = *(const float4*)(h + 1 * 256 + k);
            float4 h2 = *(const float4*)(h + 2 * 256 + k);
            float4 h3 = *(const float4*)(h + 3 * 256 + k);
            a0 += w0 * h0.x + w1 * h0.y + w2 * h0.z + w3 * h0.w;
            a1 += w0 * h1.x + w1 * h1.y + w2 * h1.z + w3 * h1.w;
            a2 += w0 * h2.x + w1 * h2.y + w2 * h2.z + w3 * h2.w;
            a3 += w0 * h3.x + w1 * h3.y + w2 * h3.z + w3 * h3.w;
        }
        gt[(half * 4 + 0) * 128 + r] = a0;
        gt[(half * 4 + 1) * 128 + r] = a1;
        gt[(half * 4 + 2) * 128 + r] = a2;
        gt[(half * 4 + 3) * 128 + r] = a3;
        __syncthreads();

        float gi = gt[ab * 128 +       aj];
        float gf = gt[ab * 128 +  32 + aj];
        float gg = gt[ab * 128 +  64 + aj];
        float go = gt[ab * 128 +  96 + aj];
        float i_ = 1.f / (1.f + __expf(-gi));
        float f_ = 1.f / (1.f + __expf(-gf));
        float g_ = tanhf(gg);
        float o_ = 1.f / (1.f + __expf(-go));
        c = f_ * c + i_ * g_;
        float hv = o_ * tanhf(c);
        hv *= m;
        c  *= m;

        out[((size_t)t * BQ + bglob_a) * (2 * HALFQ) + dir * HALFQ + s * 32 + aj] = hv;

        if (step < LQ - 1) {
            float* dst = hbuf + (p ^ 1) * 2048 + ab * 256 + (int)s * 32 + aj;
            uint32_t la = smem_u32(dst);
#pragma unroll
            for (int rk = 0; rk < 8; rk++) {
                uint32_t ra;
                asm volatile("mapa.shared::cluster.u32 %0, %1, %2;"
                             : "=r"(ra) : "r"(la), "r"(rk));
                asm volatile("st.shared::cluster.f32 [%0], %1;"
                             :: "r"(ra), "f"(hv) : "memory");
            }
            asm volatile("barrier.cluster.arrive.aligned;" ::: "memory");
        }
    }
}

// ===========================================================================
// Launch
// Inputs (metadata order): x, mask, W_ih_f, W_hh_f, b_ih_f, b_hh_f,
//                          W_ih_b, W_hh_b, b_ih_b, b_hh_b
// Output: float32 (L, B, 2*HALF)
// ===========================================================================
extern "C" void kernel_launch(void* const* d_in, const int* in_sizes, int n_in,
                              void* d_out, int out_size)
{
    const float* x     = (const float*)d_in[0];
    const float* mask  = (const float*)d_in[1];
    const float* Wihf  = (const float*)d_in[2];
    const float* Whhf  = (const float*)d_in[3];
    const float* bihf  = (const float*)d_in[4];
    const float* bhhf  = (const float*)d_in[5];
    const float* Wihb  = (const float*)d_in[6];
    const float* Whhb  = (const float*)d_in[7];
    const float* bihb  = (const float*)d_in[8];
    const float* bhhb  = (const float*)d_in[9];
    float* out = (float*)d_out;

    // Phase 0: split-bf16 conversions + bias fold
    conv_x<<<16384, 256>>>(x);
    conv_w<<<1024, 256>>>(Wihf, Wihb, bihf, bhhf, bihb, bhhb);

    // Phase 1: tensor-core (HMMA) input projection into permuted scratch
    cudaFuncSetAttribute(lstm_gemm_mma,
                         cudaFuncAttributeMaxDynamicSharedMemorySize, GEMM_SMEM);
    dim3 ggrid(16, 256);   // n-tiles fast -> x tile reuse in L2
    lstm_gemm_mma<<<ggrid, 256, GEMM_SMEM>>>();

    // Phase 2: recurrence (128 CTAs, clusters of 8)
    const int rec_smem = REC_SMEM_FLOATS * (int)sizeof(float);
    cudaFuncSetAttribute(lstm_recurrence,
                         cudaFuncAttributeMaxDynamicSharedMemorySize, rec_smem);
    lstm_recurrence<<<128, 256, rec_smem>>>(Whhf, Whhb, mask, out);
}

// round 11
// speedup vs baseline: 2.1835x; 2.0135x over previous
#include <cuda_runtime.h>
#include <cuda_bf16.h>
#include <cstdint>
#include <cmath>

// Problem constants
#define LQ    512   // sequence length
#define BQ    64    // batch
#define DQ    512   // input dim
#define HALFQ 256   // hidden per direction
#define GATES 1024  // 4*HALF

// ---------------------------------------------------------------------------
// Scratch
// g_xw: precomputed input projections (+ folded biases), permuted layout:
//   xw[dir][t][bg][slice][bl][gate*32+j]   (2*512*8*8*8*128 floats = 256 MiB)
// g_xhi/g_xlo: split-bf16 x        [32768][512]
// g_whi/g_wlo: split-bf16 Wcat     [2048][512]  (rows 0..1023 = fwd, rest bwd)
// g_bsum: b_ih + b_hh per gate row [2048]
// ---------------------------------------------------------------------------
__device__ __align__(16) float         g_xw[2ull * 512 * 8 * 8 * 8 * 128];
__device__ __align__(16) __nv_bfloat16 g_xhi[32768ull * 512];
__device__ __align__(16) __nv_bfloat16 g_xlo[32768ull * 512];
__device__ __align__(16) __nv_bfloat16 g_whi[2048ull * 512];
__device__ __align__(16) __nv_bfloat16 g_wlo[2048ull * 512];
__device__ __align__(16) float         g_bsum[2048];

// ---------------------------------------------------------------------------
// Helpers
// ---------------------------------------------------------------------------
__device__ __forceinline__ uint32_t smem_u32(const void* p) {
    uint32_t a;
    asm("{ .reg .u64 t; cvta.to.shared.u64 t, %1; cvt.u32.u64 %0, t; }"
        : "=r"(a) : "l"(p));
    return a;
}
__device__ __forceinline__ uint32_t ctarank() {
    uint32_t r;
    asm("mov.u32 %0, %%cluster_ctarank;" : "=r"(r));
    return r;
}
__device__ __forceinline__ void cp16(uint32_t dst, const void* src) {
    asm volatile("cp.async.cg.shared.global [%0], [%1], 16;"
                 :: "r"(dst), "l"(src) : "memory");
}
__device__ __forceinline__ void cp_commit() {
    asm volatile("cp.async.commit_group;" ::: "memory");
}
template <int N>
__device__ __forceinline__ void cp_wait() {
    asm volatile("cp.async.wait_group %0;" :: "n"(N) : "memory");
}
__device__ __forceinline__ void ldm_x4(uint32_t& r0, uint32_t& r1,
                                       uint32_t& r2, uint32_t& r3, uint32_t a) {
    asm volatile("ldmatrix.sync.aligned.m8n8.x4.shared.b16 {%0,%1,%2,%3}, [%4];"
                 : "=r"(r0), "=r"(r1), "=r"(r2), "=r"(r3) : "r"(a));
}
__device__ __forceinline__ void ldm_x2(uint32_t& r0, uint32_t& r1, uint32_t a) {
    asm volatile("ldmatrix.sync.aligned.m8n8.x2.shared.b16 {%0,%1}, [%2];"
                 : "=r"(r0), "=r"(r1) : "r"(a));
}
__device__ __forceinline__ void mma_bf16(float* c, const uint32_t* a,
                                         uint32_t b0, uint32_t b1) {
    asm volatile("mma.sync.aligned.m16n8k16.row.col.f32.bf16.bf16.f32 "
                 "{%0,%1,%2,%3}, {%4,%5,%6,%7}, {%8,%9}, {%0,%1,%2,%3};"
                 : "+f"(c[0]), "+f"(c[1]), "+f"(c[2]), "+f"(c[3])
                 : "r"(a[0]), "r"(a[1]), "r"(a[2]), "r"(a[3]),
                   "r"(b0), "r"(b1));
}
// accurate-enough activations via MUFU exp (error ~1e-6; validated in R8)
__device__ __forceinline__ float sigm_e(float x) {
    return __fdividef(1.f, 1.f + __expf(-x));
}
__device__ __forceinline__ float tanh_e(float x) {
    return 1.f - __fdividef(2.f, __expf(2.f * x) + 1.f);
}
__device__ __forceinline__ uint32_t pack_bf16(float a, float b) {
    return (uint32_t)__bfloat16_as_ushort(__float2bfloat16(a)) |
           ((uint32_t)__bfloat16_as_ushort(__float2bfloat16(b)) << 16);
}

// ===========================================================================
// Kernel 0a: split x into hi/lo bf16
// ===========================================================================
__global__ __launch_bounds__(256)
void conv_x(const float* __restrict__ x)
{
    size_t i = ((size_t)blockIdx.x * 256 + threadIdx.x) * 4;
    float4 v = *(const float4*)(x + i);
    float vv[4] = {v.x, v.y, v.z, v.w};
    unsigned short hi[4], lo[4];
#pragma unroll
    for (int j = 0; j < 4; j++) {
        __nv_bfloat16 h = __float2bfloat16(vv[j]);
        __nv_bfloat16 l = __float2bfloat16(vv[j] - __bfloat162float(h));
        hi[j] = __bfloat16_as_ushort(h);
        lo[j] = __bfloat16_as_ushort(l);
    }
    *(uint2*)((unsigned short*)g_xhi + i) = *(uint2*)hi;
    *(uint2*)((unsigned short*)g_xlo + i) = *(uint2*)lo;
}

// ===========================================================================
// Kernel 0b: split W into hi/lo bf16 (concat fwd|bwd), and combined biases
// ===========================================================================
__global__ __launch_bounds__(256)
void conv_w(const float* __restrict__ Wf, const float* __restrict__ Wb,
            const float* __restrict__ bihf, const float* __restrict__ bhhf,
            const float* __restrict__ bihb, const float* __restrict__ bhhb)
{
    size_t e0 = ((size_t)blockIdx.x * 256 + threadIdx.x) * 4;
    int row = (int)(e0 >> 9);
    int col = (int)(e0 & 511);
    const float* src = (row < GATES) ? (Wf + (size_t)row * 512 + col)
                                     : (Wb + (size_t)(row - GATES) * 512 + col);
    float4 v = *(const float4*)src;
    float vv[4] = {v.x, v.y, v.z, v.w};
    unsigned short hi[4], lo[4];
#pragma unroll
    for (int j = 0; j < 4; j++) {
        __nv_bfloat16 h = __float2bfloat16(vv[j]);
        __nv_bfloat16 l = __float2bfloat16(vv[j] - __bfloat162float(h));
        hi[j] = __bfloat16_as_ushort(h);
        lo[j] = __bfloat16_as_ushort(l);
    }
    *(uint2*)((unsigned short*)g_whi + e0) = *(uint2*)hi;
    *(uint2*)((unsigned short*)g_wlo + e0) = *(uint2*)lo;

    if (blockIdx.x == 0) {
        for (int n = threadIdx.x; n < 2048; n += 256) {
            int r = n & (GATES - 1);
            g_bsum[n] = (n < GATES) ? (bihf[r] + bhhf[r]) : (bihb[r] + bhhb[r]);
        }
    }
}

// ===========================================================================
// Kernel 1: mma.sync bf16 GEMM  C[32768,2048] = x @ Wcat^T + bsum
// (unchanged — validated in R8, rel_err 6e-6)
// ===========================================================================
#define STG_HALF 20480                      // halves per stage (4 * 128*40)
#define GEMM_SMEM (3 * STG_HALF * 2)        // 122880 bytes

__device__ __forceinline__ void stage_load(uint32_t smbase, int st,
                                           int m0, int n0, int k0, int tid)
{
    const __nv_bfloat16* const xh = g_xhi + (size_t)m0 * 512 + k0;
    const __nv_bfloat16* const xl = g_xlo + (size_t)m0 * 512 + k0;
    const __nv_bfloat16* const wh = g_whi + (size_t)n0 * 512 + k0;
    const __nv_bfloat16* const wl = g_wlo + (size_t)n0 * 512 + k0;
    const uint32_t sbase = smbase + st * (STG_HALF * 2);
    const int r0  = tid >> 2;          // 0..63
    const int seg = tid & 3;           // 0..3

#pragma unroll
    for (int mat = 0; mat < 4; mat++) {
        const __nv_bfloat16* src =
            (mat == 0) ? xh : (mat == 1) ? xl : (mat == 2) ? wh : wl;
#pragma unroll
        for (int hh = 0; hh < 2; hh++) {
            int row = r0 + hh * 64;
            uint32_t dst = sbase + (uint32_t)(mat * 10240 + row * 80 + seg * 16);
            cp16(dst, src + (size_t)row * 512 + seg * 8);
        }
    }
}

__global__ __launch_bounds__(256)
void lstm_gemm_mma()
{
    extern __shared__ char smg[];
    const uint32_t smbase = smem_u32(smg);
    const int tid  = threadIdx.x;
    const int lane = tid & 31;
    const int wid  = tid >> 5;
    const int wm = (wid & 3) * 32;          // warp m offset
    const int wn = (wid >> 2) * 64;         // warp n offset
    const int n0 = blockIdx.x * 128;        // 16 n-tiles (fast -> x reuse in L2)
    const int m0 = blockIdx.y * 128;        // 256 m-tiles

    float acc[2][8][4];
#pragma unroll
    for (int i = 0; i < 2; i++)
#pragma unroll
        for (int j = 0; j < 8; j++)
#pragma unroll
            for (int q = 0; q < 4; q++) acc[i][j][q] = 0.f;

    const uint32_t a_row = (uint32_t)(lane & 15);
    const uint32_t a_col = (uint32_t)((lane >> 4) * 8);
    const uint32_t b_row = (uint32_t)((lane & 7) + ((lane >> 4) << 3));
    const uint32_t b_col = (uint32_t)(((lane >> 3) & 1) * 8);

    stage_load(smbase, 0, m0, n0, 0, tid);  cp_commit();
    stage_load(smbase, 1, m0, n0, 32, tid); cp_commit();

    for (int c = 0; c < 16; c++) {
        if (c + 2 < 16) stage_load(smbase, (c + 2) % 3, m0, n0, (c + 2) * 32, tid);
        cp_commit();
        cp_wait<2>();
        __syncthreads();

        uint32_t sb  = smbase + (uint32_t)((c % 3) * (STG_HALF * 2));
        uint32_t sAh = sb;
        uint32_t sAl = sb + 10240;
        uint32_t sBh = sb + 20480;
        uint32_t sBl = sb + 30720;

#pragma unroll
        for (int kk = 0; kk < 2; kk++) {
            const uint32_t kb = (uint32_t)(kk * 32);

            uint32_t ah[2][4], al[2][4];
#pragma unroll
            for (int tm = 0; tm < 2; tm++) {
                uint32_t roff = (uint32_t)(wm + tm * 16) + a_row;
                uint32_t off = roff * 80 + kb + a_col * 2;
                ldm_x4(ah[tm][0], ah[tm][1], ah[tm][2], ah[tm][3], sAh + off);
                ldm_x4(al[tm][0], al[tm][1], al[tm][2], al[tm][3], sAl + off);
            }

            uint32_t b[16];
#pragma unroll
            for (int p = 0; p < 4; p++) {
                uint32_t roff = (uint32_t)(wn + p * 16) + b_row;
                uint32_t off = roff * 80 + kb + b_col * 2;
                ldm_x4(b[p * 4 + 0], b[p * 4 + 1], b[p * 4 + 2], b[p * 4 + 3],
                       sBh + off);
            }
#pragma unroll
            for (int tm = 0; tm < 2; tm++)
#pragma unroll
                for (int tn = 0; tn < 8; tn++) {
                    mma_bf16(acc[tm][tn], ah[tm], b[tn * 2], b[tn * 2 + 1]);
                    mma_bf16(acc[tm][tn], al[tm], b[tn * 2], b[tn * 2 + 1]);
                }
#pragma unroll
            for (int p = 0; p < 4; p++) {
                uint32_t roff = (uint32_t)(wn + p * 16) + b_row;
                uint32_t off = roff * 80 + kb + b_col * 2;
                ldm_x4(b[p * 4 + 0], b[p * 4 + 1], b[p * 4 + 2], b[p * 4 + 3],
                       sBl + off);
            }
#pragma unroll
            for (int tm = 0; tm < 2; tm++)
#pragma unroll
                for (int tn = 0; tn < 8; tn++)
                    mma_bf16(acc[tm][tn], ah[tm], b[tn * 2], b[tn * 2 + 1]);
        }
        __syncthreads();
    }

#pragma unroll
    for (int tm = 0; tm < 2; tm++) {
#pragma unroll
        for (int tn = 0; tn < 8; tn++) {
            const int n    = n0 + wn + tn * 8 + (lane & 3) * 2;
            const int dir  = n >> 10;
            const int rowg = n & (GATES - 1);
            const int gate = rowg >> 8;
            const int slc  = (rowg >> 5) & 7;
            const int j    = rowg & 31;
            float b0 = g_bsum[n];
            float b1 = g_bsum[n + 1];
#pragma unroll
            for (int rr = 0; rr < 2; rr++) {
                const int m  = m0 + wm + tm * 16 + (lane >> 2) + rr * 8;
                const int t  = m >> 6;
                const int bq = m & 63;
                size_t base = (((((size_t)dir * LQ + t) * 8 + (bq >> 3)) * 8 + slc) * 8
                               + (bq & 7)) * 128 + gate * 32 + j;
                float2 v;
                v.x = acc[tm][tn][rr * 2 + 0] + b0;
                v.y = acc[tm][tn][rr * 2 + 1] + b1;
                *(float2*)&g_xw[base] = v;
            }
        }
    }
}

// ===========================================================================
// Kernel 2: recurrence via HMMA. Cluster of 8 CTAs per (dir, batch-group).
// W_hh slice lives in REGISTERS as split-bf16 mma A-fragments (loaded once).
// Per step: gates[128x8] = W(128x256) @ h(256x8) as 8 warps x m16n8k16 chain,
// 3 passes (Whi*hhi + Whi*hlo + Wlo*hhi), acc initialized from prefetched xW.
// h broadcast to 8 CTAs as bf16 hi/lo via DSMEM; one cluster barrier per step.
// R10 fix: xW t-stride is 65536 floats (was wrongly 8192); exact-exp activations.
// ===========================================================================
#define HPITCH 264   // halves per h row (8 batches x 256 k, padded: 528B rows)

__global__ void __cluster_dims__(8, 1, 1) __launch_bounds__(256, 1)
lstm_recurrence(const float* __restrict__ Whh_f,
                const float* __restrict__ Whh_b,
                const float* __restrict__ mask,
                float* __restrict__ out)
{
    __shared__ __align__(16) __nv_bfloat16 sh_hi[2][8][HPITCH];
    __shared__ __align__(16) __nv_bfloat16 sh_lo[2][8][HPITCH];
    __shared__ float gt[8][132];

    const int tid  = threadIdx.x;
    const int lane = tid & 31;
    const int w    = tid >> 5;               // warp = 16-row slab of gates
    const uint32_t s = ctarank();            // cluster rank = h-slice
    const int gid = blockIdx.x >> 3;         // 0..15
    const int dir = gid >> 3;                // 0 fwd, 1 bwd
    const int bg  = gid & 7;                 // batch group (8 batches)

    const float* Whh = dir ? Whh_b : Whh_f;

    // ---- load W_hh slice into mma A-fragments (split bf16 hi/lo), once ----
    // local gate row r in [0,128): global row = (r>>5)*256 + s*32 + (r&31)
    // warp w owns rows [16w, 16w+16); lane holds rows r0 = 16w+(lane>>2), r0+8
    const int r0 = 16 * w + (lane >> 2);
    const int r1 = r0 + 8;
    const int grow0 = ((r0 >> 5) << 8) | ((int)s << 5) | (r0 & 31);
    const int grow1 = ((r1 >> 5) << 8) | ((int)s << 5) | (r1 & 31);
    const int kc = (lane & 3) * 2;

    uint32_t ahi[16][4], alo[16][4];
#pragma unroll
    for (int kt = 0; kt < 16; kt++) {
        const int kb = kt * 16 + kc;
#pragma unroll
        for (int q = 0; q < 4; q++) {
            const int gr = (q & 1) ? grow1 : grow0;
            const int kk = kb + ((q >> 1) ? 8 : 0);
            float2 f = *(const float2*)&Whh[(size_t)gr * 256 + kk];
            float hx = __bfloat162float(__float2bfloat16(f.x));
            float hy = __bfloat162float(__float2bfloat16(f.y));
            ahi[kt][q] = pack_bf16(f.x, f.y);
            alo[kt][q] = pack_bf16(f.x - hx, f.y - hy);
        }
    }
    // Fragment reg order expected by mma: {(r0,k), (r1,k), (r0,k+8), (r1,k+8)}

    // zero phase-0 h buffers only (phase 1 is fully overwritten by stores)
    for (int idx = tid; idx < 8 * HPITCH; idx += 256) {
        sh_hi[0][0][idx] = __float2bfloat16(0.f);
        sh_lo[0][0][idx] = __float2bfloat16(0.f);
    }
    __syncthreads();

    // B-fragment ldmatrix addresses: rows = batch, lanes 0-7 col 0, 8-15 col +8
    const uint32_t hbase  = smem_u32(&sh_hi[0][0][0]);
    const uint32_t lo_off = smem_u32(&sh_lo[0][0][0]) - hbase;
    const uint32_t ldm_off = (uint32_t)((lane & 7) * (HPITCH * 2)
                                        + (((lane >> 3) & 1) * 16));
    const uint32_t phase_sz = (uint32_t)(8 * HPITCH * 2);

    // activation role: one (batch, h-index) per thread
    const int ab = tid >> 5;
    const int aj = tid & 31;
    const int bglob_a = bg * 8 + ab;
    // gt store addresses for acc: c0=(r0,b0) c1=(r0,b0+1) c2=(r1,b0) c3=(r1,b0+1)
    const int bcol = (lane & 3) * 2;

    // DSMEM target (local) for this thread's h element, phase written = p^1
    const uint32_t my_hoff = (uint32_t)(ab * (HPITCH * 2) + ((int)s * 32 + aj) * 2);

    float c = 0.f;

    // base for (dir, bg, s); per-t stride in the permuted layout is
    // 8(bg)*8(slice)*8(bl)*128 = 65536 floats  (R10 bugfix: was 8192)
    const float* xw_g = g_xw + ((size_t)dir * LQ * 64 + (size_t)bg * 8 + s) * 1024;

#pragma unroll 1
    for (int step = 0; step < LQ; step++) {
        const int t = dir ? (LQ - 1 - step) : step;
        const int p = step & 1;

        // ---- prefetch (independent of h) BEFORE the cluster wait ----
        const float* xwp = xw_g + (size_t)t * 65536;
        float acc[4];
        acc[0] = xwp[bcol * 128 + r0];
        acc[1] = xwp[(bcol + 1) * 128 + r0];
        acc[2] = xwp[bcol * 128 + r1];
        acc[3] = xwp[(bcol + 1) * 128 + r1];
        float m = __ldg(&mask[t * BQ + bglob_a]);

        if (step > 0)
            asm volatile("barrier.cluster.wait.aligned;" ::: "memory");

        // ---- matvec: 16 k-tiles x (hi*hi + hi*lo + lo*hi) ----
        const uint32_t hb = hbase + (uint32_t)p * phase_sz + ldm_off;
#pragma unroll
        for (int kt = 0; kt < 16; kt++) {
            uint32_t bh0, bh1, bl0, bl1;
            ldm_x2(bh0, bh1, hb + kt * 32);
            ldm_x2(bl0, bl1, hb + lo_off + kt * 32);
            mma_bf16(acc, ahi[kt], bh0, bh1);
            mma_bf16(acc, ahi[kt], bl0, bl1);
            mma_bf16(acc, alo[kt], bh0, bh1);
        }

        // ---- gates to smem ----
        gt[bcol][r0]     = acc[0];
        gt[bcol + 1][r0] = acc[1];
        gt[bcol][r1]     = acc[2];
        gt[bcol + 1][r1] = acc[3];
        __syncthreads();

        // ---- activations (exact-exp forms, ~1e-6 error) ----
        float gi = gt[ab][aj];
        float gf = gt[ab][32 + aj];
        float gg = gt[ab][64 + aj];
        float go = gt[ab][96 + aj];
        float i_ = sigm_e(gi);
        float f_ = sigm_e(gf);
        float g_ = tanh_e(gg);
        float o_ = sigm_e(go);
        c = f_ * c + i_ * g_;
        float hv = o_ * tanh_e(c);
        hv *= m;
        c  *= m;

        out[((size_t)t * BQ + bglob_a) * (2 * HALFQ) + dir * HALFQ + s * 32 + aj] = hv;

        if (step < LQ - 1) {
            // broadcast split-bf16 h to all 8 CTAs' next-phase buffers
            unsigned short hhi = __bfloat16_as_ushort(__float2bfloat16(hv));
            float hv_hi = __bfloat162float(__ushort_as_bfloat16(hhi));
            unsigned short hlo = __bfloat16_as_ushort(__float2bfloat16(hv - hv_hi));
            uint32_t la = hbase + (uint32_t)(p ^ 1) * phase_sz + my_hoff;
#pragma unroll
            for (int rk = 0; rk < 8; rk++) {
                uint32_t ra;
                asm volatile("mapa.shared::cluster.u32 %0, %1, %2;"
                             : "=r"(ra) : "r"(la), "r"(rk));
                asm volatile("st.shared::cluster.b16 [%0], %1;"
                             :: "r"(ra), "h"(hhi) : "memory");
                asm volatile("st.shared::cluster.b16 [%0], %1;"
                             :: "r"(ra + lo_off), "h"(hlo) : "memory");
            }
            asm volatile("barrier.cluster.arrive.aligned;" ::: "memory");
        }
    }
}

// ===========================================================================
// Launch
// Inputs (metadata order): x, mask, W_ih_f, W_hh_f, b_ih_f, b_hh_f,
//                          W_ih_b, W_hh_b, b_ih_b, b_hh_b
// Output: float32 (L, B, 2*HALF)
// ===========================================================================
extern "C" void kernel_launch(void* const* d_in, const int* in_sizes, int n_in,
                              void* d_out, int out_size)
{
    const float* x     = (const float*)d_in[0];
    const float* mask  = (const float*)d_in[1];
    const float* Wihf  = (const float*)d_in[2];
    const float* Whhf  = (const float*)d_in[3];
    const float* bihf  = (const float*)d_in[4];
    const float* bhhf  = (const float*)d_in[5];
    const float* Wihb  = (const float*)d_in[6];
    const float* Whhb  = (const float*)d_in[7];
    const float* bihb  = (const float*)d_in[8];
    const float* bhhb  = (const float*)d_in[9];
    float* out = (float*)d_out;

    // Phase 0: split-bf16 conversions + bias fold
    conv_x<<<16384, 256>>>(x);
    conv_w<<<1024, 256>>>(Wihf, Wihb, bihf, bhhf, bihb, bhhb);

    // Phase 1: tensor-core (HMMA) input projection into permuted scratch
    cudaFuncSetAttribute(lstm_gemm_mma,
                         cudaFuncAttributeMaxDynamicSharedMemorySize, GEMM_SMEM);
    dim3 ggrid(16, 256);   // n-tiles fast -> x tile reuse in L2
    lstm_gemm_mma<<<ggrid, 256, GEMM_SMEM>>>();

    // Phase 2: recurrence (128 CTAs, clusters of 8), HMMA matvec
    lstm_recurrence<<<128, 256>>>(Whhf, Whhb, mask, out);
}

// round 12
// speedup vs baseline: 2.3197x; 1.0624x over previous
#include <cuda_runtime.h>
#include <cuda_bf16.h>
#include <cstdint>
#include <cmath>

// Problem constants
#define LQ    512   // sequence length
#define BQ    64    // batch
#define DQ    512   // input dim
#define HALFQ 256   // hidden per direction
#define GATES 1024  // 4*HALF

// ---------------------------------------------------------------------------
// Scratch
// g_xw: precomputed input projections (+ folded biases), permuted layout:
//   xw[dir][t][bg][slice][bl][gate*32+j]   (2*512*8*8*8*128 floats = 256 MiB)
// g_xhi/g_xlo: split-bf16 x        [32768][512]
// g_whi/g_wlo: split-bf16 Wcat     [2048][512]  (rows 0..1023 = fwd, rest bwd)
// g_bsum: b_ih + b_hh per gate row [2048]
// ---------------------------------------------------------------------------
__device__ __align__(16) float         g_xw[2ull * 512 * 8 * 8 * 8 * 128];
__device__ __align__(16) __nv_bfloat16 g_xhi[32768ull * 512];
__device__ __align__(16) __nv_bfloat16 g_xlo[32768ull * 512];
__device__ __align__(16) __nv_bfloat16 g_whi[2048ull * 512];
__device__ __align__(16) __nv_bfloat16 g_wlo[2048ull * 512];
__device__ __align__(16) float         g_bsum[2048];

// ---------------------------------------------------------------------------
// Helpers
// ---------------------------------------------------------------------------
__device__ __forceinline__ uint32_t smem_u32(const void* p) {
    uint32_t a;
    asm("{ .reg .u64 t; cvta.to.shared.u64 t, %1; cvt.u32.u64 %0, t; }"
        : "=r"(a) : "l"(p));
    return a;
}
__device__ __forceinline__ uint32_t ctarank() {
    uint32_t r;
    asm("mov.u32 %0, %%cluster_ctarank;" : "=r"(r));
    return r;
}
__device__ __forceinline__ void cp16(uint32_t dst, const void* src) {
    asm volatile("cp.async.cg.shared.global [%0], [%1], 16;"
                 :: "r"(dst), "l"(src) : "memory");
}
__device__ __forceinline__ void cp_commit() {
    asm volatile("cp.async.commit_group;" ::: "memory");
}
template <int N>
__device__ __forceinline__ void cp_wait() {
    asm volatile("cp.async.wait_group %0;" :: "n"(N) : "memory");
}
__device__ __forceinline__ void ldm_x4(uint32_t& r0, uint32_t& r1,
                                       uint32_t& r2, uint32_t& r3, uint32_t a) {
    asm volatile("ldmatrix.sync.aligned.m8n8.x4.shared.b16 {%0,%1,%2,%3}, [%4];"
                 : "=r"(r0), "=r"(r1), "=r"(r2), "=r"(r3) : "r"(a));
}
__device__ __forceinline__ void ldm_x2(uint32_t& r0, uint32_t& r1, uint32_t a) {
    asm volatile("ldmatrix.sync.aligned.m8n8.x2.shared.b16 {%0,%1}, [%2];"
                 : "=r"(r0), "=r"(r1) : "r"(a));
}
__device__ __forceinline__ void mma_bf16(float* c, const uint32_t* a,
                                         uint32_t b0, uint32_t b1) {
    asm volatile("mma.sync.aligned.m16n8k16.row.col.f32.bf16.bf16.f32 "
                 "{%0,%1,%2,%3}, {%4,%5,%6,%7}, {%8,%9}, {%0,%1,%2,%3};"
                 : "+f"(c[0]), "+f"(c[1]), "+f"(c[2]), "+f"(c[3])
                 : "r"(a[0]), "r"(a[1]), "r"(a[2]), "r"(a[3]),
                   "r"(b0), "r"(b1));
}
// accurate activations via MUFU exp (error ~1e-6; validated in R8/R11)
__device__ __forceinline__ float sigm_e(float x) {
    return __fdividef(1.f, 1.f + __expf(-x));
}
__device__ __forceinline__ float tanh_e(float x) {
    return 1.f - __fdividef(2.f, __expf(2.f * x) + 1.f);
}
__device__ __forceinline__ uint32_t pack_bf16(float a, float b) {
    return (uint32_t)__bfloat16_as_ushort(__float2bfloat16(a)) |
           ((uint32_t)__bfloat16_as_ushort(__float2bfloat16(b)) << 16);
}

// ===========================================================================
// Kernel 0a: split x into hi/lo bf16
// ===========================================================================
__global__ __launch_bounds__(256)
void conv_x(const float* __restrict__ x)
{
    size_t i = ((size_t)blockIdx.x * 256 + threadIdx.x) * 4;
    float4 v = *(const float4*)(x + i);
    float vv[4] = {v.x, v.y, v.z, v.w};
    unsigned short hi[4], lo[4];
#pragma unroll
    for (int j = 0; j < 4; j++) {
        __nv_bfloat16 h = __float2bfloat16(vv[j]);
        __nv_bfloat16 l = __float2bfloat16(vv[j] - __bfloat162float(h));
        hi[j] = __bfloat16_as_ushort(h);
        lo[j] = __bfloat16_as_ushort(l);
    }
    *(uint2*)((unsigned short*)g_xhi + i) = *(uint2*)hi;
    *(uint2*)((unsigned short*)g_xlo + i) = *(uint2*)lo;
}

// ===========================================================================
// Kernel 0b: split W into hi/lo bf16 (concat fwd|bwd), and combined biases
// ===========================================================================
__global__ __launch_bounds__(256)
void conv_w(const float* __restrict__ Wf, const float* __restrict__ Wb,
            const float* __restrict__ bihf, const float* __restrict__ bhhf,
            const float* __restrict__ bihb, const float* __restrict__ bhhb)
{
    size_t e0 = ((size_t)blockIdx.x * 256 + threadIdx.x) * 4;
    int row = (int)(e0 >> 9);
    int col = (int)(e0 & 511);
    const float* src = (row < GATES) ? (Wf + (size_t)row * 512 + col)
                                     : (Wb + (size_t)(row - GATES) * 512 + col);
    float4 v = *(const float4*)src;
    float vv[4] = {v.x, v.y, v.z, v.w};
    unsigned short hi[4], lo[4];
#pragma unroll
    for (int j = 0; j < 4; j++) {
        __nv_bfloat16 h = __float2bfloat16(vv[j]);
        __nv_bfloat16 l = __float2bfloat16(vv[j] - __bfloat162float(h));
        hi[j] = __bfloat16_as_ushort(h);
        lo[j] = __bfloat16_as_ushort(l);
    }
    *(uint2*)((unsigned short*)g_whi + e0) = *(uint2*)hi;
    *(uint2*)((unsigned short*)g_wlo + e0) = *(uint2*)lo;

    if (blockIdx.x == 0) {
        for (int n = threadIdx.x; n < 2048; n += 256) {
            int r = n & (GATES - 1);
            g_bsum[n] = (n < GATES) ? (bihf[r] + bhhf[r]) : (bihb[r] + bhhb[r]);
        }
    }
}

// ===========================================================================
// Kernel 1: mma.sync bf16 GEMM  C[32768,2048] = x @ Wcat^T + bsum
// (unchanged — validated in R8/R11, rel_err 6e-6)
// ===========================================================================
#define STG_HALF 20480                      // halves per stage (4 * 128*40)
#define GEMM_SMEM (3 * STG_HALF * 2)        // 122880 bytes

__device__ __forceinline__ void stage_load(uint32_t smbase, int st,
                                           int m0, int n0, int k0, int tid)
{
    const __nv_bfloat16* const xh = g_xhi + (size_t)m0 * 512 + k0;
    const __nv_bfloat16* const xl = g_xlo + (size_t)m0 * 512 + k0;
    const __nv_bfloat16* const wh = g_whi + (size_t)n0 * 512 + k0;
    const __nv_bfloat16* const wl = g_wlo + (size_t)n0 * 512 + k0;
    const uint32_t sbase = smbase + st * (STG_HALF * 2);
    const int r0  = tid >> 2;          // 0..63
    const int seg = tid & 3;           // 0..3

#pragma unroll
    for (int mat = 0; mat < 4; mat++) {
        const __nv_bfloat16* src =
            (mat == 0) ? xh : (mat == 1) ? xl : (mat == 2) ? wh : wl;
#pragma unroll
        for (int hh = 0; hh < 2; hh++) {
            int row = r0 + hh * 64;
            uint32_t dst = sbase + (uint32_t)(mat * 10240 + row * 80 + seg * 16);
            cp16(dst, src + (size_t)row * 512 + seg * 8);
        }
    }
}

__global__ __launch_bounds__(256)
void lstm_gemm_mma()
{
    extern __shared__ char smg[];
    const uint32_t smbase = smem_u32(smg);
    const int tid  = threadIdx.x;
    const int lane = tid & 31;
    const int wid  = tid >> 5;
    const int wm = (wid & 3) * 32;          // warp m offset
    const int wn = (wid >> 2) * 64;         // warp n offset
    const int n0 = blockIdx.x * 128;        // 16 n-tiles (fast -> x reuse in L2)
    const int m0 = blockIdx.y * 128;        // 256 m-tiles

    float acc[2][8][4];
#pragma unroll
    for (int i = 0; i < 2; i++)
#pragma unroll
        for (int j = 0; j < 8; j++)
#pragma unroll
            for (int q = 0; q < 4; q++) acc[i][j][q] = 0.f;

    const uint32_t a_row = (uint32_t)(lane & 15);
    const uint32_t a_col = (uint32_t)((lane >> 4) * 8);
    const uint32_t b_row = (uint32_t)((lane & 7) + ((lane >> 4) << 3));
    const uint32_t b_col = (uint32_t)(((lane >> 3) & 1) * 8);

    stage_load(smbase, 0, m0, n0, 0, tid);  cp_commit();
    stage_load(smbase, 1, m0, n0, 32, tid); cp_commit();

    for (int c = 0; c < 16; c++) {
        if (c + 2 < 16) stage_load(smbase, (c + 2) % 3, m0, n0, (c + 2) * 32, tid);
        cp_commit();
        cp_wait<2>();
        __syncthreads();

        uint32_t sb  = smbase + (uint32_t)((c % 3) * (STG_HALF * 2));
        uint32_t sAh = sb;
        uint32_t sAl = sb + 10240;
        uint32_t sBh = sb + 20480;
        uint32_t sBl = sb + 30720;

#pragma unroll
        for (int kk = 0; kk < 2; kk++) {
            const uint32_t kb = (uint32_t)(kk * 32);

            uint32_t ah[2][4], al[2][4];
#pragma unroll
            for (int tm = 0; tm < 2; tm++) {
                uint32_t roff = (uint32_t)(wm + tm * 16) + a_row;
                uint32_t off = roff * 80 + kb + a_col * 2;
                ldm_x4(ah[tm][0], ah[tm][1], ah[tm][2], ah[tm][3], sAh + off);
                ldm_x4(al[tm][0], al[tm][1], al[tm][2], al[tm][3], sAl + off);
            }

            uint32_t b[16];
#pragma unroll
            for (int p = 0; p < 4; p++) {
                uint32_t roff = (uint32_t)(wn + p * 16) + b_row;
                uint32_t off = roff * 80 + kb + b_col * 2;
                ldm_x4(b[p * 4 + 0], b[p * 4 + 1], b[p * 4 + 2], b[p * 4 + 3],
                       sBh + off);
            }
#pragma unroll
            for (int tm = 0; tm < 2; tm++)
#pragma unroll
                for (int tn = 0; tn < 8; tn++) {
                    mma_bf16(acc[tm][tn], ah[tm], b[tn * 2], b[tn * 2 + 1]);
                    mma_bf16(acc[tm][tn], al[tm], b[tn * 2], b[tn * 2 + 1]);
                }
#pragma unroll
            for (int p = 0; p < 4; p++) {
                uint32_t roff = (uint32_t)(wn + p * 16) + b_row;
                uint32_t off = roff * 80 + kb + b_col * 2;
                ldm_x4(b[p * 4 + 0], b[p * 4 + 1], b[p * 4 + 2], b[p * 4 + 3],
                       sBl + off);
            }
#pragma unroll
            for (int tm = 0; tm < 2; tm++)
#pragma unroll
                for (int tn = 0; tn < 8; tn++)
                    mma_bf16(acc[tm][tn], ah[tm], b[tn * 2], b[tn * 2 + 1]);
        }
        __syncthreads();
    }

#pragma unroll
    for (int tm = 0; tm < 2; tm++) {
#pragma unroll
        for (int tn = 0; tn < 8; tn++) {
            const int n    = n0 + wn + tn * 8 + (lane & 3) * 2;
            const int dir  = n >> 10;
            const int rowg = n & (GATES - 1);
            const int gate = rowg >> 8;
            const int slc  = (rowg >> 5) & 7;
            const int j    = rowg & 31;
            float b0 = g_bsum[n];
            float b1 = g_bsum[n + 1];
#pragma unroll
            for (int rr = 0; rr < 2; rr++) {
                const int m  = m0 + wm + tm * 16 + (lane >> 2) + rr * 8;
                const int t  = m >> 6;
                const int bq = m & 63;
                size_t base = (((((size_t)dir * LQ + t) * 8 + (bq >> 3)) * 8 + slc) * 8
                               + (bq & 7)) * 128 + gate * 32 + j;
                float2 v;
                v.x = acc[tm][tn][rr * 2 + 0] + b0;
                v.y = acc[tm][tn][rr * 2 + 1] + b1;
                *(float2*)&g_xw[base] = v;
            }
        }
    }
}

// ===========================================================================
// Kernel 2: recurrence via HMMA. Cluster of 8 CTAs per (dir, batch-group).
// W_hh slice lives in REGISTERS as split-bf16 mma A-fragments (loaded once).
// R12: the 48 per-step MMAs now run as THREE INDEPENDENT 16-deep chains
// (accA = xW + Whi*h_hi, accB = Whi*h_lo, accC = Wlo*h_hi) summed at the
// gate write — breaks the serial RAW accumulation chain (3x MMA ILP).
// ===========================================================================
#define HPITCH 264   // halves per h row (8 batches x 256 k, padded: 528B rows)

__global__ void __cluster_dims__(8, 1, 1) __launch_bounds__(256, 1)
lstm_recurrence(const float* __restrict__ Whh_f,
                const float* __restrict__ Whh_b,
                const float* __restrict__ mask,
                float* __restrict__ out)
{
    __shared__ __align__(16) __nv_bfloat16 sh_hi[2][8][HPITCH];
    __shared__ __align__(16) __nv_bfloat16 sh_lo[2][8][HPITCH];
    __shared__ float gt[8][132];

    const int tid  = threadIdx.x;
    const int lane = tid & 31;
    const int w    = tid >> 5;               // warp = 16-row slab of gates
    const uint32_t s = ctarank();            // cluster rank = h-slice
    const int gid = blockIdx.x >> 3;         // 0..15
    const int dir = gid >> 3;                // 0 fwd, 1 bwd
    const int bg  = gid & 7;                 // batch group (8 batches)

    const float* Whh = dir ? Whh_b : Whh_f;

    // ---- load W_hh slice into mma A-fragments (split bf16 hi/lo), once ----
    const int r0 = 16 * w + (lane >> 2);
    const int r1 = r0 + 8;
    const int grow0 = ((r0 >> 5) << 8) | ((int)s << 5) | (r0 & 31);
    const int grow1 = ((r1 >> 5) << 8) | ((int)s << 5) | (r1 & 31);
    const int kc = (lane & 3) * 2;

    uint32_t ahi[16][4], alo[16][4];
#pragma unroll
    for (int kt = 0; kt < 16; kt++) {
        const int kb = kt * 16 + kc;
#pragma unroll
        for (int q = 0; q < 4; q++) {
            const int gr = (q & 1) ? grow1 : grow0;
            const int kk = kb + ((q >> 1) ? 8 : 0);
            float2 f = *(const float2*)&Whh[(size_t)gr * 256 + kk];
            float hx = __bfloat162float(__float2bfloat16(f.x));
            float hy = __bfloat162float(__float2bfloat16(f.y));
            ahi[kt][q] = pack_bf16(f.x, f.y);
            alo[kt][q] = pack_bf16(f.x - hx, f.y - hy);
        }
    }
    // Fragment reg order expected by mma: {(r0,k), (r1,k), (r0,k+8), (r1,k+8)}

    // zero phase-0 h buffers only (phase 1 is fully overwritten by stores)
    for (int idx = tid; idx < 8 * HPITCH; idx += 256) {
        sh_hi[0][0][idx] = __float2bfloat16(0.f);
        sh_lo[0][0][idx] = __float2bfloat16(0.f);
    }
    __syncthreads();

    // B-fragment ldmatrix addresses: rows = batch, lanes 0-7 col 0, 8-15 col +8
    const uint32_t hbase  = smem_u32(&sh_hi[0][0][0]);
    const uint32_t lo_off = smem_u32(&sh_lo[0][0][0]) - hbase;
    const uint32_t ldm_off = (uint32_t)((lane & 7) * (HPITCH * 2)
                                        + (((lane >> 3) & 1) * 16));
    const uint32_t phase_sz = (uint32_t)(8 * HPITCH * 2);

    // activation role: one (batch, h-index) per thread
    const int ab = tid >> 5;
    const int aj = tid & 31;
    const int bglob_a = bg * 8 + ab;
    const int bcol = (lane & 3) * 2;

    // DSMEM target (local) for this thread's h element, phase written = p^1
    const uint32_t my_hoff = (uint32_t)(ab * (HPITCH * 2) + ((int)s * 32 + aj) * 2);

    float c = 0.f;

    // base for (dir, bg, s); per-t stride = 65536 floats (validated R11)
    const float* xw_g = g_xw + ((size_t)dir * LQ * 64 + (size_t)bg * 8 + s) * 1024;

#pragma unroll 1
    for (int step = 0; step < LQ; step++) {
        const int t = dir ? (LQ - 1 - step) : step;
        const int p = step & 1;

        // ---- prefetch (independent of h) BEFORE the cluster wait ----
        const float* xwp = xw_g + (size_t)t * 65536;
        float accA[4], accB[4], accC[4];
        accA[0] = xwp[bcol * 128 + r0];
        accA[1] = xwp[(bcol + 1) * 128 + r0];
        accA[2] = xwp[bcol * 128 + r1];
        accA[3] = xwp[(bcol + 1) * 128 + r1];
#pragma unroll
        for (int q = 0; q < 4; q++) { accB[q] = 0.f; accC[q] = 0.f; }
        float m = __ldg(&mask[t * BQ + bglob_a]);

        if (step > 0)
            asm volatile("barrier.cluster.wait.aligned;" ::: "memory");

        // ---- matvec: 16 k-tiles, 3 independent accumulation chains ----
        const uint32_t hb = hbase + (uint32_t)p * phase_sz + ldm_off;
#pragma unroll
        for (int kt = 0; kt < 16; kt++) {
            uint32_t bh0, bh1, bl0, bl1;
            ldm_x2(bh0, bh1, hb + kt * 32);
            ldm_x2(bl0, bl1, hb + lo_off + kt * 32);
            mma_bf16(accA, ahi[kt], bh0, bh1);
            mma_bf16(accB, ahi[kt], bl0, bl1);
            mma_bf16(accC, alo[kt], bh0, bh1);
        }

        // ---- gates to smem (sum the three chains here) ----
        gt[bcol][r0]     = accA[0] + accB[0] + accC[0];
        gt[bcol + 1][r0] = accA[1] + accB[1] + accC[1];
        gt[bcol][r1]     = accA[2] + accB[2] + accC[2];
        gt[bcol + 1][r1] = accA[3] + accB[3] + accC[3];
        __syncthreads();

        // ---- activations (exact-exp forms, ~1e-6 error) ----
        float gi = gt[ab][aj];
        float gf = gt[ab][32 + aj];
        float gg = gt[ab][64 + aj];
        float go = gt[ab][96 + aj];
        float i_ = sigm_e(gi);
        float f_ = sigm_e(gf);
        float g_ = tanh_e(gg);
        float o_ = sigm_e(go);
        c = f_ * c + i_ * g_;
        float hv = o_ * tanh_e(c);
        hv *= m;
        c  *= m;

        out[((size_t)t * BQ + bglob_a) * (2 * HALFQ) + dir * HALFQ + s * 32 + aj] = hv;

        if (step < LQ - 1) {
            // broadcast split-bf16 h to all 8 CTAs' next-phase buffers
            unsigned short hhi = __bfloat16_as_ushort(__float2bfloat16(hv));
            float hv_hi = __bfloat162float(__ushort_as_bfloat16(hhi));
            unsigned short hlo = __bfloat16_as_ushort(__float2bfloat16(hv - hv_hi));
            uint32_t la = hbase + (uint32_t)(p ^ 1) * phase_sz + my_hoff;
#pragma unroll
            for (int rk = 0; rk < 8; rk++) {
                uint32_t ra;
                asm volatile("mapa.shared::cluster.u32 %0, %1, %2;"
                             : "=r"(ra) : "r"(la), "r"(rk));
                asm volatile("st.shared::cluster.b16 [%0], %1;"
                             :: "r"(ra), "h"(hhi) : "memory");
                asm volatile("st.shared::cluster.b16 [%0], %1;"
                             :: "r"(ra + lo_off), "h"(hlo) : "memory");
            }
            asm volatile("barrier.cluster.arrive.aligned;" ::: "memory");
        }
    }
}

// ===========================================================================
// Launch
// Inputs (metadata order): x, mask, W_ih_f, W_hh_f, b_ih_f, b_hh_f,
//                          W_ih_b, W_hh_b, b_ih_b, b_hh_b
// Output: float32 (L, B, 2*HALF)
// ===========================================================================
extern "C" void kernel_launch(void* const* d_in, const int* in_sizes, int n_in,
                              void* d_out, int out_size)
{
    const float* x     = (const float*)d_in[0];
    const float* mask  = (const float*)d_in[1];
    const float* Wihf  = (const float*)d_in[2];
    const float* Whhf  = (const float*)d_in[3];
    const float* bihf  = (const float*)d_in[4];
    const float* bhhf  = (const float*)d_in[5];
    const float* Wihb  = (const float*)d_in[6];
    const float* Whhb  = (const float*)d_in[7];
    const float* bihb  = (const float*)d_in[8];
    const float* bhhb  = (const float*)d_in[9];
    float* out = (float*)d_out;

    // Phase 0: split-bf16 conversions + bias fold
    conv_x<<<16384, 256>>>(x);
    conv_w<<<1024, 256>>>(Wihf, Wihb, bihf, bhhf, bihb, bhhb);

    // Phase 1: tensor-core (HMMA) input projection into permuted scratch
    cudaFuncSetAttribute(lstm_gemm_mma,
                         cudaFuncAttributeMaxDynamicSharedMemorySize, GEMM_SMEM);
    dim3 ggrid(16, 256);   // n-tiles fast -> x tile reuse in L2
    lstm_gemm_mma<<<ggrid, 256, GEMM_SMEM>>>();

    // Phase 2: recurrence (128 CTAs, clusters of 8), HMMA matvec w/ 3-chain ILP
    lstm_recurrence<<<128, 256>>>(Whhf, Whhb, mask, out);
}

// round 13
// speedup vs baseline: 2.6686x; 1.1504x over previous
#include <cuda_runtime.h>
#include <cuda_bf16.h>
#include <cstdint>
#include <cmath>

// Problem constants
#define LQ    512   // sequence length
#define BQ    64    // batch
#define DQ    512   // input dim
#define HALFQ 256   // hidden per direction
#define GATES 1024  // 4*HALF

// ---------------------------------------------------------------------------
// Scratch
// g_xw: precomputed input projections (+ folded biases), permuted layout:
//   xw[dir][t][bg][slice][bl][gate*32+j]   (2*512*8*8*8*128 floats = 256 MiB)
// g_xhi/g_xlo: split-bf16 x        [32768][512]
// g_whi/g_wlo: split-bf16 Wcat     [2048][512]  (rows 0..1023 = fwd, rest bwd)
// g_bsum: b_ih + b_hh per gate row [2048]
// ---------------------------------------------------------------------------
__device__ __align__(16) float         g_xw[2ull * 512 * 8 * 8 * 8 * 128];
__device__ __align__(16) __nv_bfloat16 g_xhi[32768ull * 512];
__device__ __align__(16) __nv_bfloat16 g_xlo[32768ull * 512];
__device__ __align__(16) __nv_bfloat16 g_whi[2048ull * 512];
__device__ __align__(16) __nv_bfloat16 g_wlo[2048ull * 512];
__device__ __align__(16) float         g_bsum[2048];

// ---------------------------------------------------------------------------
// Helpers
// ---------------------------------------------------------------------------
__device__ __forceinline__ uint32_t smem_u32(const void* p) {
    uint32_t a;
    asm("{ .reg .u64 t; cvta.to.shared.u64 t, %1; cvt.u32.u64 %0, t; }"
        : "=r"(a) : "l"(p));
    return a;
}
__device__ __forceinline__ uint32_t ctarank() {
    uint32_t r;
    asm("mov.u32 %0, %%cluster_ctarank;" : "=r"(r));
    return r;
}
__device__ __forceinline__ void cp16(uint32_t dst, const void* src) {
    asm volatile("cp.async.cg.shared.global [%0], [%1], 16;"
                 :: "r"(dst), "l"(src) : "memory");
}
__device__ __forceinline__ void cp_commit() {
    asm volatile("cp.async.commit_group;" ::: "memory");
}
template <int N>
__device__ __forceinline__ void cp_wait() {
    asm volatile("cp.async.wait_group %0;" :: "n"(N) : "memory");
}
__device__ __forceinline__ void ldm_x4(uint32_t& r0, uint32_t& r1,
                                       uint32_t& r2, uint32_t& r3, uint32_t a) {
    asm volatile("ldmatrix.sync.aligned.m8n8.x4.shared.b16 {%0,%1,%2,%3}, [%4];"
                 : "=r"(r0), "=r"(r1), "=r"(r2), "=r"(r3) : "r"(a));
}
__device__ __forceinline__ void ldm_x2(uint32_t& r0, uint32_t& r1, uint32_t a) {
    asm volatile("ldmatrix.sync.aligned.m8n8.x2.shared.b16 {%0,%1}, [%2];"
                 : "=r"(r0), "=r"(r1) : "r"(a));
}
__device__ __forceinline__ void mma_bf16(float* c, const uint32_t* a,
                                         uint32_t b0, uint32_t b1) {
    asm volatile("mma.sync.aligned.m16n8k16.row.col.f32.bf16.bf16.f32 "
                 "{%0,%1,%2,%3}, {%4,%5,%6,%7}, {%8,%9}, {%0,%1,%2,%3};"
                 : "+f"(c[0]), "+f"(c[1]), "+f"(c[2]), "+f"(c[3])
                 : "r"(a[0]), "r"(a[1]), "r"(a[2]), "r"(a[3]),
                   "r"(b0), "r"(b1));
}
// accurate activations via MUFU exp (error ~1e-6; validated R8/R11/R12)
__device__ __forceinline__ float sigm_e(float x) {
    return __fdividef(1.f, 1.f + __expf(-x));
}
__device__ __forceinline__ float tanh_e(float x) {
    return 1.f - __fdividef(2.f, __expf(2.f * x) + 1.f);
}
__device__ __forceinline__ uint32_t pack_bf16(float a, float b) {
    return (uint32_t)__bfloat16_as_ushort(__float2bfloat16(a)) |
           ((uint32_t)__bfloat16_as_ushort(__float2bfloat16(b)) << 16);
}

// ===========================================================================
// Kernel 0a: split x into hi/lo bf16
// ===========================================================================
__global__ __launch_bounds__(256)
void conv_x(const float* __restrict__ x)
{
    size_t i = ((size_t)blockIdx.x * 256 + threadIdx.x) * 4;
    float4 v = *(const float4*)(x + i);
    float vv[4] = {v.x, v.y, v.z, v.w};
    unsigned short hi[4], lo[4];
#pragma unroll
    for (int j = 0; j < 4; j++) {
        __nv_bfloat16 h = __float2bfloat16(vv[j]);
        __nv_bfloat16 l = __float2bfloat16(vv[j] - __bfloat162float(h));
        hi[j] = __bfloat16_as_ushort(h);
        lo[j] = __bfloat16_as_ushort(l);
    }
    *(uint2*)((unsigned short*)g_xhi + i) = *(uint2*)hi;
    *(uint2*)((unsigned short*)g_xlo + i) = *(uint2*)lo;
}

// ===========================================================================
// Kernel 0b: split W into hi/lo bf16 (concat fwd|bwd), and combined biases
// ===========================================================================
__global__ __launch_bounds__(256)
void conv_w(const float* __restrict__ Wf, const float* __restrict__ Wb,
            const float* __restrict__ bihf, const float* __restrict__ bhhf,
            const float* __restrict__ bihb, const float* __restrict__ bhhb)
{
    size_t e0 = ((size_t)blockIdx.x * 256 + threadIdx.x) * 4;
    int row = (int)(e0 >> 9);
    int col = (int)(e0 & 511);
    const float* src = (row < GATES) ? (Wf + (size_t)row * 512 + col)
                                     : (Wb + (size_t)(row - GATES) * 512 + col);
    float4 v = *(const float4*)src;
    float vv[4] = {v.x, v.y, v.z, v.w};
    unsigned short hi[4], lo[4];
#pragma unroll
    for (int j = 0; j < 4; j++) {
        __nv_bfloat16 h = __float2bfloat16(vv[j]);
        __nv_bfloat16 l = __float2bfloat16(vv[j] - __bfloat162float(h));
        hi[j] = __bfloat16_as_ushort(h);
        lo[j] = __bfloat16_as_ushort(l);
    }
    *(uint2*)((unsigned short*)g_whi + e0) = *(uint2*)hi;
    *(uint2*)((unsigned short*)g_wlo + e0) = *(uint2*)lo;

    if (blockIdx.x == 0) {
        for (int n = threadIdx.x; n < 2048; n += 256) {
            int r = n & (GATES - 1);
            g_bsum[n] = (n < GATES) ? (bihf[r] + bhhf[r]) : (bihb[r] + bhhb[r]);
        }
    }
}

// ===========================================================================
// Kernel 1: mma.sync bf16 GEMM  C[32768,2048] = x @ Wcat^T + bsum
// (unchanged — validated R8/R11/R12, rel_err 6e-6)
// ===========================================================================
#define STG_HALF 20480                      // halves per stage (4 * 128*40)
#define GEMM_SMEM (3 * STG_HALF * 2)        // 122880 bytes

__device__ __forceinline__ void stage_load(uint32_t smbase, int st,
                                           int m0, int n0, int k0, int tid)
{
    const __nv_bfloat16* const xh = g_xhi + (size_t)m0 * 512 + k0;
    const __nv_bfloat16* const xl = g_xlo + (size_t)m0 * 512 + k0;
    const __nv_bfloat16* const wh = g_whi + (size_t)n0 * 512 + k0;
    const __nv_bfloat16* const wl = g_wlo + (size_t)n0 * 512 + k0;
    const uint32_t sbase = smbase + st * (STG_HALF * 2);
    const int r0  = tid >> 2;          // 0..63
    const int seg = tid & 3;           // 0..3

#pragma unroll
    for (int mat = 0; mat < 4; mat++) {
        const __nv_bfloat16* src =
            (mat == 0) ? xh : (mat == 1) ? xl : (mat == 2) ? wh : wl;
#pragma unroll
        for (int hh = 0; hh < 2; hh++) {
            int row = r0 + hh * 64;
            uint32_t dst = sbase + (uint32_t)(mat * 10240 + row * 80 + seg * 16);
            cp16(dst, src + (size_t)row * 512 + seg * 8);
        }
    }
}

__global__ __launch_bounds__(256)
void lstm_gemm_mma()
{
    extern __shared__ char smg[];
    const uint32_t smbase = smem_u32(smg);
    const int tid  = threadIdx.x;
    const int lane = tid & 31;
    const int wid  = tid >> 5;
    const int wm = (wid & 3) * 32;          // warp m offset
    const int wn = (wid >> 2) * 64;         // warp n offset
    const int n0 = blockIdx.x * 128;        // 16 n-tiles (fast -> x reuse in L2)
    const int m0 = blockIdx.y * 128;        // 256 m-tiles

    float acc[2][8][4];
#pragma unroll
    for (int i = 0; i < 2; i++)
#pragma unroll
        for (int j = 0; j < 8; j++)
#pragma unroll
            for (int q = 0; q < 4; q++) acc[i][j][q] = 0.f;

    const uint32_t a_row = (uint32_t)(lane & 15);
    const uint32_t a_col = (uint32_t)((lane >> 4) * 8);
    const uint32_t b_row = (uint32_t)((lane & 7) + ((lane >> 4) << 3));
    const uint32_t b_col = (uint32_t)(((lane >> 3) & 1) * 8);

    stage_load(smbase, 0, m0, n0, 0, tid);  cp_commit();
    stage_load(smbase, 1, m0, n0, 32, tid); cp_commit();

    for (int c = 0; c < 16; c++) {
        if (c + 2 < 16) stage_load(smbase, (c + 2) % 3, m0, n0, (c + 2) * 32, tid);
        cp_commit();
        cp_wait<2>();
        __syncthreads();

        uint32_t sb  = smbase + (uint32_t)((c % 3) * (STG_HALF * 2));
        uint32_t sAh = sb;
        uint32_t sAl = sb + 10240;
        uint32_t sBh = sb + 20480;
        uint32_t sBl = sb + 30720;

#pragma unroll
        for (int kk = 0; kk < 2; kk++) {
            const uint32_t kb = (uint32_t)(kk * 32);

            uint32_t ah[2][4], al[2][4];
#pragma unroll
            for (int tm = 0; tm < 2; tm++) {
                uint32_t roff = (uint32_t)(wm + tm * 16) + a_row;
                uint32_t off = roff * 80 + kb + a_col * 2;
                ldm_x4(ah[tm][0], ah[tm][1], ah[tm][2], ah[tm][3], sAh + off);
                ldm_x4(al[tm][0], al[tm][1], al[tm][2], al[tm][3], sAl + off);
            }

            uint32_t b[16];
#pragma unroll
            for (int p = 0; p < 4; p++) {
                uint32_t roff = (uint32_t)(wn + p * 16) + b_row;
                uint32_t off = roff * 80 + kb + b_col * 2;
                ldm_x4(b[p * 4 + 0], b[p * 4 + 1], b[p * 4 + 2], b[p * 4 + 3],
                       sBh + off);
            }
#pragma unroll
            for (int tm = 0; tm < 2; tm++)
#pragma unroll
                for (int tn = 0; tn < 8; tn++) {
                    mma_bf16(acc[tm][tn], ah[tm], b[tn * 2], b[tn * 2 + 1]);
                    mma_bf16(acc[tm][tn], al[tm], b[tn * 2], b[tn * 2 + 1]);
                }
#pragma unroll
            for (int p = 0; p < 4; p++) {
                uint32_t roff = (uint32_t)(wn + p * 16) + b_row;
                uint32_t off = roff * 80 + kb + b_col * 2;
                ldm_x4(b[p * 4 + 0], b[p * 4 + 1], b[p * 4 + 2], b[p * 4 + 3],
                       sBl + off);
            }
#pragma unroll
            for (int tm = 0; tm < 2; tm++)
#pragma unroll
                for (int tn = 0; tn < 8; tn++)
                    mma_bf16(acc[tm][tn], ah[tm], b[tn * 2], b[tn * 2 + 1]);
        }
        __syncthreads();
    }

#pragma unroll
    for (int tm = 0; tm < 2; tm++) {
#pragma unroll
        for (int tn = 0; tn < 8; tn++) {
            const int n    = n0 + wn + tn * 8 + (lane & 3) * 2;
            const int dir  = n >> 10;
            const int rowg = n & (GATES - 1);
            const int gate = rowg >> 8;
            const int slc  = (rowg >> 5) & 7;
            const int j    = rowg & 31;
            float b0 = g_bsum[n];
            float b1 = g_bsum[n + 1];
#pragma unroll
            for (int rr = 0; rr < 2; rr++) {
                const int m  = m0 + wm + tm * 16 + (lane >> 2) + rr * 8;
                const int t  = m >> 6;
                const int bq = m & 63;
                size_t base = (((((size_t)dir * LQ + t) * 8 + (bq >> 3)) * 8 + slc) * 8
                               + (bq & 7)) * 128 + gate * 32 + j;
                float2 v;
                v.x = acc[tm][tn][rr * 2 + 0] + b0;
                v.y = acc[tm][tn][rr * 2 + 1] + b1;
                *(float2*)&g_xw[base] = v;
            }
        }
    }
}

// ===========================================================================
// Kernel 2: recurrence via HMMA. Cluster of 8 CTAs per (dir, batch-group).
// R13: 512 threads (16 warps) per CTA. Warp w owns row-slab (w>>1, 16 rows)
// and K-HALF (w&1, 128 of 256) -> W frags halve to 64 regs/thread, 4 warps
// per SMSP for latency hiding, MMA chains of depth 8. Partial gates from the
// two k-halves land in gtp[2][..]; activations sum both planes + xW (whose
// loads are issued at loop-top and consumed only after syncthreads).
// ===========================================================================
#define HPITCH 264   // halves per h row (8 batches x 256 k, padded: 528B rows)

__global__ void __cluster_dims__(8, 1, 1) __launch_bounds__(512, 1)
lstm_recurrence(const float* __restrict__ Whh_f,
                const float* __restrict__ Whh_b,
                const float* __restrict__ mask,
                float* __restrict__ out)
{
    __shared__ __align__(16) __nv_bfloat16 sh_hi[2][8][HPITCH];
    __shared__ __align__(16) __nv_bfloat16 sh_lo[2][8][HPITCH];
    __shared__ float gtp[2][8][132];

    const int tid  = threadIdx.x;
    const int lane = tid & 31;
    const int w    = tid >> 5;               // 0..15
    const int rs   = w >> 1;                 // row slab (16 rows)
    const int kh   = w & 1;                  // k half (128 k)
    const uint32_t s = ctarank();            // cluster rank = h-slice
    const int gid = blockIdx.x >> 3;         // 0..15
    const int dir = gid >> 3;                // 0 fwd, 1 bwd
    const int bg  = gid & 7;                 // batch group (8 batches)

    const float* Whh = dir ? Whh_b : Whh_f;

    // ---- load W_hh slice into mma A-fragments (split bf16 hi/lo), once ----
    // local gate row r in [0,128): global row = (r>>5)*256 + s*32 + (r&31)
    const int r0 = 16 * rs + (lane >> 2);
    const int r1 = r0 + 8;
    const int grow0 = ((r0 >> 5) << 8) | ((int)s << 5) | (r0 & 31);
    const int grow1 = ((r1 >> 5) << 8) | ((int)s << 5) | (r1 & 31);
    const int kc = (lane & 3) * 2;

    uint32_t ahi[8][4], alo[8][4];
#pragma unroll
    for (int kt = 0; kt < 8; kt++) {
        const int kb = kh * 128 + kt * 16 + kc;
#pragma unroll
        for (int q = 0; q < 4; q++) {
            const int gr = (q & 1) ? grow1 : grow0;
            const int kk = kb + ((q >> 1) ? 8 : 0);
            float2 f = *(const float2*)&Whh[(size_t)gr * 256 + kk];
            float hx = __bfloat162float(__float2bfloat16(f.x));
            float hy = __bfloat162float(__float2bfloat16(f.y));
            ahi[kt][q] = pack_bf16(f.x, f.y);
            alo[kt][q] = pack_bf16(f.x - hx, f.y - hy);
        }
    }
    // Fragment reg order expected by mma: {(r0,k), (r1,k), (r0,k+8), (r1,k+8)}

    // zero phase-0 h buffers only (phase 1 is fully overwritten by stores)
    for (int idx = tid; idx < 8 * HPITCH; idx += 512) {
        sh_hi[0][0][idx] = __float2bfloat16(0.f);
        sh_lo[0][0][idx] = __float2bfloat16(0.f);
    }
    __syncthreads();

    // B-fragment ldmatrix addressing: rows = batch; this warp reads its k-half
    const uint32_t hbase  = smem_u32(&sh_hi[0][0][0]);
    const uint32_t lo_off = smem_u32(&sh_lo[0][0][0]) - hbase;
    const uint32_t ldm_off = (uint32_t)((lane & 7) * (HPITCH * 2)
                                        + (((lane >> 3) & 1) * 16)
                                        + kh * 256);   // k-half: 128 halves = 256B
    const uint32_t phase_sz = (uint32_t)(8 * HPITCH * 2);

    // activation role: threads 0..255, one (batch, h-index) each
    const int ab = (tid >> 5) & 7;
    const int aj = tid & 31;
    const int bglob_a = bg * 8 + ab;
    const int bcol = (lane & 3) * 2;

    // DSMEM target (local) for this thread's h element, phase written = p^1
    const uint32_t my_hoff = (uint32_t)(ab * (HPITCH * 2) + ((int)s * 32 + aj) * 2);

    float c = 0.f;

    // base for (dir, bg, s); per-t stride = 65536 floats (validated R11)
    const float* xw_g = g_xw + ((size_t)dir * LQ * 64 + (size_t)bg * 8 + s) * 1024;

#pragma unroll 1
    for (int step = 0; step < LQ; step++) {
        const int t = dir ? (LQ - 1 - step) : step;
        const int p = step & 1;

        // ---- prefetch (independent of h) BEFORE the cluster wait;
        //      consumed only after syncthreads -> full-step latency cover ----
        const float* xwp = xw_g + (size_t)t * 65536;
        float xwv0 = 0.f, xwv1 = 0.f, xwv2 = 0.f, xwv3 = 0.f, m = 0.f;
        if (tid < 256) {
            xwv0 = xwp[ab * 128 +       aj];
            xwv1 = xwp[ab * 128 +  32 + aj];
            xwv2 = xwp[ab * 128 +  64 + aj];
            xwv3 = xwp[ab * 128 +  96 + aj];
            m    = __ldg(&mask[t * BQ + bglob_a]);
        }
        float accA[4] = {0.f, 0.f, 0.f, 0.f};
        float accB[4] = {0.f, 0.f, 0.f, 0.f};
        float accC[4] = {0.f, 0.f, 0.f, 0.f};

        if (step > 0)
            asm volatile("barrier.cluster.wait.aligned;" ::: "memory");

        // ---- matvec over this warp's k-half: 8 k-tiles, 3 indep chains ----
        const uint32_t hb = hbase + (uint32_t)p * phase_sz + ldm_off;
#pragma unroll
        for (int kt = 0; kt < 8; kt++) {
            uint32_t bh0, bh1, bl0, bl1;
            ldm_x2(bh0, bh1, hb + kt * 32);
            ldm_x2(bl0, bl1, hb + lo_off + kt * 32);
            mma_bf16(accA, ahi[kt], bh0, bh1);
            mma_bf16(accB, ahi[kt], bl0, bl1);
            mma_bf16(accC, alo[kt], bh0, bh1);
        }

        // ---- partial gates to smem (per k-half plane) ----
        gtp[kh][bcol][r0]     = accA[0] + accB[0] + accC[0];
        gtp[kh][bcol + 1][r0] = accA[1] + accB[1] + accC[1];
        gtp[kh][bcol][r1]     = accA[2] + accB[2] + accC[2];
        gtp[kh][bcol + 1][r1] = accA[3] + accB[3] + accC[3];
        __syncthreads();

        // ---- activations (threads 0..255) ----
        unsigned short hhi = 0, hlo = 0;
        if (tid < 256) {
            float gi = gtp[0][ab][aj]      + gtp[1][ab][aj]      + xwv0;
            float gf = gtp[0][ab][32 + aj] + gtp[1][ab][32 + aj] + xwv1;
            float gg = gtp[0][ab][64 + aj] + gtp[1][ab][64 + aj] + xwv2;
            float go = gtp[0][ab][96 + aj] + gtp[1][ab][96 + aj] + xwv3;
            float i_ = sigm_e(gi);
            float f_ = sigm_e(gf);
            float g_ = tanh_e(gg);
            float o_ = sigm_e(go);
            c = f_ * c + i_ * g_;
            float hv = o_ * tanh_e(c);
            hv *= m;
            c  *= m;

            out[((size_t)t * BQ + bglob_a) * (2 * HALFQ) + dir * HALFQ
                + s * 32 + aj] = hv;

            hhi = __bfloat16_as_ushort(__float2bfloat16(hv));
            float hv_hi = __bfloat162float(__ushort_as_bfloat16(hhi));
            hlo = __bfloat16_as_ushort(__float2bfloat16(hv - hv_hi));
        }

        if (step < LQ - 1) {
            if (tid < 256) {
                // broadcast split-bf16 h to all 8 CTAs' next-phase buffers
                uint32_t la = hbase + (uint32_t)(p ^ 1) * phase_sz + my_hoff;
#pragma unroll
                for (int rk = 0; rk < 8; rk++) {
                    uint32_t ra;
                    asm volatile("mapa.shared::cluster.u32 %0, %1, %2;"
                                 : "=r"(ra) : "r"(la), "r"(rk));
                    asm volatile("st.shared::cluster.b16 [%0], %1;"
                                 :: "r"(ra), "h"(hhi) : "memory");
                    asm volatile("st.shared::cluster.b16 [%0], %1;"
                                 :: "r"(ra + lo_off), "h"(hlo) : "memory");
                }
            }
            asm volatile("barrier.cluster.arrive.aligned;" ::: "memory");
        }
    }
}

// ===========================================================================
// Launch
// Inputs (metadata order): x, mask, W_ih_f, W_hh_f, b_ih_f, b_hh_f,
//                          W_ih_b, W_hh_b, b_ih_b, b_hh_b
// Output: float32 (L, B, 2*HALF)
// ===========================================================================
extern "C" void kernel_launch(void* const* d_in, const int* in_sizes, int n_in,
                              void* d_out, int out_size)
{
    const float* x     = (const float*)d_in[0];
    const float* mask  = (const float*)d_in[1];
    const float* Wihf  = (const float*)d_in[2];
    const float* Whhf  = (const float*)d_in[3];
    const float* bihf  = (const float*)d_in[4];
    const float* bhhf  = (const float*)d_in[5];
    const float* Wihb  = (const float*)d_in[6];
    const float* Whhb  = (const float*)d_in[7];
    const float* bihb  = (const float*)d_in[8];
    const float* bhhb  = (const float*)d_in[9];
    float* out = (float*)d_out;

    // Phase 0: split-bf16 conversions + bias fold
    conv_x<<<16384, 256>>>(x);
    conv_w<<<1024, 256>>>(Wihf, Wihb, bihf, bhhf, bihb, bhhb);

    // Phase 1: tensor-core (HMMA) input projection into permuted scratch
    cudaFuncSetAttribute(lstm_gemm_mma,
                         cudaFuncAttributeMaxDynamicSharedMemorySize, GEMM_SMEM);
    dim3 ggrid(16, 256);   // n-tiles fast -> x tile reuse in L2
    lstm_gemm_mma<<<ggrid, 256, GEMM_SMEM>>>();

    // Phase 2: recurrence (128 CTAs x 512 thr, clusters of 8), k-split warps
    lstm_recurrence<<<128, 512>>>(Whhf, Whhb, mask, out);
}

// round 14
// speedup vs baseline: 2.6918x; 1.0087x over previous
#include <cuda_runtime.h>
#include <cuda_bf16.h>
#include <cstdint>
#include <cmath>

// Problem constants
#define LQ    512   // sequence length
#define BQ    64    // batch
#define DQ    512   // input dim
#define HALFQ 256   // hidden per direction
#define GATES 1024  // 4*HALF

// ---------------------------------------------------------------------------
// Scratch
// g_xw: precomputed input projections (+ folded biases), permuted layout:
//   xw[dir][t][bg][slice][bl][gate*32+j]   (2*512*8*8*8*128 floats = 256 MiB)
// g_xhi/g_xlo: split-bf16 x        [32768][512]
// g_whi/g_wlo: split-bf16 Wcat     [2048][512]  (rows 0..1023 = fwd, rest bwd)
// g_bsum: b_ih + b_hh per gate row [2048]
// ---------------------------------------------------------------------------
__device__ __align__(16) float         g_xw[2ull * 512 * 8 * 8 * 8 * 128];
__device__ __align__(16) __nv_bfloat16 g_xhi[32768ull * 512];
__device__ __align__(16) __nv_bfloat16 g_xlo[32768ull * 512];
__device__ __align__(16) __nv_bfloat16 g_whi[2048ull * 512];
__device__ __align__(16) __nv_bfloat16 g_wlo[2048ull * 512];
__device__ __align__(16) float         g_bsum[2048];

// ---------------------------------------------------------------------------
// Helpers
// ---------------------------------------------------------------------------
__device__ __forceinline__ uint32_t smem_u32(const void* p) {
    uint32_t a;
    asm("{ .reg .u64 t; cvta.to.shared.u64 t, %1; cvt.u32.u64 %0, t; }"
        : "=r"(a) : "l"(p));
    return a;
}
__device__ __forceinline__ uint32_t ctarank() {
    uint32_t r;
    asm("mov.u32 %0, %%cluster_ctarank;" : "=r"(r));
    return r;
}
__device__ __forceinline__ void cp16(uint32_t dst, const void* src) {
    asm volatile("cp.async.cg.shared.global [%0], [%1], 16;"
                 :: "r"(dst), "l"(src) : "memory");
}
__device__ __forceinline__ void cp_commit() {
    asm volatile("cp.async.commit_group;" ::: "memory");
}
template <int N>
__device__ __forceinline__ void cp_wait() {
    asm volatile("cp.async.wait_group %0;" :: "n"(N) : "memory");
}
__device__ __forceinline__ void ldm_x4(uint32_t& r0, uint32_t& r1,
                                       uint32_t& r2, uint32_t& r3, uint32_t a) {
    asm volatile("ldmatrix.sync.aligned.m8n8.x4.shared.b16 {%0,%1,%2,%3}, [%4];"
                 : "=r"(r0), "=r"(r1), "=r"(r2), "=r"(r3) : "r"(a));
}
__device__ __forceinline__ void ldm_x2(uint32_t& r0, uint32_t& r1, uint32_t a) {
    asm volatile("ldmatrix.sync.aligned.m8n8.x2.shared.b16 {%0,%1}, [%2];"
                 : "=r"(r0), "=r"(r1) : "r"(a));
}
__device__ __forceinline__ void mma_bf16(float* c, const uint32_t* a,
                                         uint32_t b0, uint32_t b1) {
    asm volatile("mma.sync.aligned.m16n8k16.row.col.f32.bf16.bf16.f32 "
                 "{%0,%1,%2,%3}, {%4,%5,%6,%7}, {%8,%9}, {%0,%1,%2,%3};"
                 : "+f"(c[0]), "+f"(c[1]), "+f"(c[2]), "+f"(c[3])
                 : "r"(a[0]), "r"(a[1]), "r"(a[2]), "r"(a[3]),
                   "r"(b0), "r"(b1));
}
// accurate activations via MUFU exp (error ~1e-6; validated R8/R11-R13)
__device__ __forceinline__ float sigm_e(float x) {
    return __fdividef(1.f, 1.f + __expf(-x));
}
__device__ __forceinline__ float tanh_e(float x) {
    return 1.f - __fdividef(2.f, __expf(2.f * x) + 1.f);
}
__device__ __forceinline__ uint32_t pack_bf16(float a, float b) {
    return (uint32_t)__bfloat16_as_ushort(__float2bfloat16(a)) |
           ((uint32_t)__bfloat16_as_ushort(__float2bfloat16(b)) << 16);
}

// ===========================================================================
// Kernel 0a: split x into hi/lo bf16
// ===========================================================================
__global__ __launch_bounds__(256)
void conv_x(const float* __restrict__ x)
{
    size_t i = ((size_t)blockIdx.x * 256 + threadIdx.x) * 4;
    float4 v = *(const float4*)(x + i);
    float vv[4] = {v.x, v.y, v.z, v.w};
    unsigned short hi[4], lo[4];
#pragma unroll
    for (int j = 0; j < 4; j++) {
        __nv_bfloat16 h = __float2bfloat16(vv[j]);
        __nv_bfloat16 l = __float2bfloat16(vv[j] - __bfloat162float(h));
        hi[j] = __bfloat16_as_ushort(h);
        lo[j] = __bfloat16_as_ushort(l);
    }
    *(uint2*)((unsigned short*)g_xhi + i) = *(uint2*)hi;
    *(uint2*)((unsigned short*)g_xlo + i) = *(uint2*)lo;
}

// ===========================================================================
// Kernel 0b: split W into hi/lo bf16 (concat fwd|bwd), and combined biases
// ===========================================================================
__global__ __launch_bounds__(256)
void conv_w(const float* __restrict__ Wf, const float* __restrict__ Wb,
            const float* __restrict__ bihf, const float* __restrict__ bhhf,
            const float* __restrict__ bihb, const float* __restrict__ bhhb)
{
    size_t e0 = ((size_t)blockIdx.x * 256 + threadIdx.x) * 4;
    int row = (int)(e0 >> 9);
    int col = (int)(e0 & 511);
    const float* src = (row < GATES) ? (Wf + (size_t)row * 512 + col)
                                     : (Wb + (size_t)(row - GATES) * 512 + col);
    float4 v = *(const float4*)src;
    float vv[4] = {v.x, v.y, v.z, v.w};
    unsigned short hi[4], lo[4];
#pragma unroll
    for (int j = 0; j < 4; j++) {
        __nv_bfloat16 h = __float2bfloat16(vv[j]);
        __nv_bfloat16 l = __float2bfloat16(vv[j] - __bfloat162float(h));
        hi[j] = __bfloat16_as_ushort(h);
        lo[j] = __bfloat16_as_ushort(l);
    }
    *(uint2*)((unsigned short*)g_whi + e0) = *(uint2*)hi;
    *(uint2*)((unsigned short*)g_wlo + e0) = *(uint2*)lo;

    if (blockIdx.x == 0) {
        for (int n = threadIdx.x; n < 2048; n += 256) {
            int r = n & (GATES - 1);
            g_bsum[n] = (n < GATES) ? (bihf[r] + bhhf[r]) : (bihb[r] + bhhb[r]);
        }
    }
}

// ===========================================================================
// Kernel 1: mma.sync bf16 GEMM  C[32768,2048] = x @ Wcat^T + bsum
// (unchanged — validated R8/R11-R13, rel_err 6e-6)
// ===========================================================================
#define STG_HALF 20480                      // halves per stage (4 * 128*40)
#define GEMM_SMEM (3 * STG_HALF * 2)        // 122880 bytes

__device__ __forceinline__ void stage_load(uint32_t smbase, int st,
                                           int m0, int n0, int k0, int tid)
{
    const __nv_bfloat16* const xh = g_xhi + (size_t)m0 * 512 + k0;
    const __nv_bfloat16* const xl = g_xlo + (size_t)m0 * 512 + k0;
    const __nv_bfloat16* const wh = g_whi + (size_t)n0 * 512 + k0;
    const __nv_bfloat16* const wl = g_wlo + (size_t)n0 * 512 + k0;
    const uint32_t sbase = smbase + st * (STG_HALF * 2);
    const int r0  = tid >> 2;          // 0..63
    const int seg = tid & 3;           // 0..3

#pragma unroll
    for (int mat = 0; mat < 4; mat++) {
        const __nv_bfloat16* src =
            (mat == 0) ? xh : (mat == 1) ? xl : (mat == 2) ? wh : wl;
#pragma unroll
        for (int hh = 0; hh < 2; hh++) {
            int row = r0 + hh * 64;
            uint32_t dst = sbase + (uint32_t)(mat * 10240 + row * 80 + seg * 16);
            cp16(dst, src + (size_t)row * 512 + seg * 8);
        }
    }
}

__global__ __launch_bounds__(256)
void lstm_gemm_mma()
{
    extern __shared__ char smg[];
    const uint32_t smbase = smem_u32(smg);
    const int tid  = threadIdx.x;
    const int lane = tid & 31;
    const int wid  = tid >> 5;
    const int wm = (wid & 3) * 32;          // warp m offset
    const int wn = (wid >> 2) * 64;         // warp n offset
    const int n0 = blockIdx.x * 128;        // 16 n-tiles (fast -> x reuse in L2)
    const int m0 = blockIdx.y * 128;        // 256 m-tiles

    float acc[2][8][4];
#pragma unroll
    for (int i = 0; i < 2; i++)
#pragma unroll
        for (int j = 0; j < 8; j++)
#pragma unroll
            for (int q = 0; q < 4; q++) acc[i][j][q] = 0.f;

    const uint32_t a_row = (uint32_t)(lane & 15);
    const uint32_t a_col = (uint32_t)((lane >> 4) * 8);
    const uint32_t b_row = (uint32_t)((lane & 7) + ((lane >> 4) << 3));
    const uint32_t b_col = (uint32_t)(((lane >> 3) & 1) * 8);

    stage_load(smbase, 0, m0, n0, 0, tid);  cp_commit();
    stage_load(smbase, 1, m0, n0, 32, tid); cp_commit();

    for (int c = 0; c < 16; c++) {
        if (c + 2 < 16) stage_load(smbase, (c + 2) % 3, m0, n0, (c + 2) * 32, tid);
        cp_commit();
        cp_wait<2>();
        __syncthreads();

        uint32_t sb  = smbase + (uint32_t)((c % 3) * (STG_HALF * 2));
        uint32_t sAh = sb;
        uint32_t sAl = sb + 10240;
        uint32_t sBh = sb + 20480;
        uint32_t sBl = sb + 30720;

#pragma unroll
        for (int kk = 0; kk < 2; kk++) {
            const uint32_t kb = (uint32_t)(kk * 32);

            uint32_t ah[2][4], al[2][4];
#pragma unroll
            for (int tm = 0; tm < 2; tm++) {
                uint32_t roff = (uint32_t)(wm + tm * 16) + a_row;
                uint32_t off = roff * 80 + kb + a_col * 2;
                ldm_x4(ah[tm][0], ah[tm][1], ah[tm][2], ah[tm][3], sAh + off);
                ldm_x4(al[tm][0], al[tm][1], al[tm][2], al[tm][3], sAl + off);
            }

            uint32_t b[16];
#pragma unroll
            for (int p = 0; p < 4; p++) {
                uint32_t roff = (uint32_t)(wn + p * 16) + b_row;
                uint32_t off = roff * 80 + kb + b_col * 2;
                ldm_x4(b[p * 4 + 0], b[p * 4 + 1], b[p * 4 + 2], b[p * 4 + 3],
                       sBh + off);
            }
#pragma unroll
            for (int tm = 0; tm < 2; tm++)
#pragma unroll
                for (int tn = 0; tn < 8; tn++) {
                    mma_bf16(acc[tm][tn], ah[tm], b[tn * 2], b[tn * 2 + 1]);
                    mma_bf16(acc[tm][tn], al[tm], b[tn * 2], b[tn * 2 + 1]);
                }
#pragma unroll
            for (int p = 0; p < 4; p++) {
                uint32_t roff = (uint32_t)(wn + p * 16) + b_row;
                uint32_t off = roff * 80 + kb + b_col * 2;
                ldm_x4(b[p * 4 + 0], b[p * 4 + 1], b[p * 4 + 2], b[p * 4 + 3],
                       sBl + off);
            }
#pragma unroll
            for (int tm = 0; tm < 2; tm++)
#pragma unroll
                for (int tn = 0; tn < 8; tn++)
                    mma_bf16(acc[tm][tn], ah[tm], b[tn * 2], b[tn * 2 + 1]);
        }
        __syncthreads();
    }

#pragma unroll
    for (int tm = 0; tm < 2; tm++) {
#pragma unroll
        for (int tn = 0; tn < 8; tn++) {
            const int n    = n0 + wn + tn * 8 + (lane & 3) * 2;
            const int dir  = n >> 10;
            const int rowg = n & (GATES - 1);
            const int gate = rowg >> 8;
            const int slc  = (rowg >> 5) & 7;
            const int j    = rowg & 31;
            float b0 = g_bsum[n];
            float b1 = g_bsum[n + 1];
#pragma unroll
            for (int rr = 0; rr < 2; rr++) {
                const int m  = m0 + wm + tm * 16 + (lane >> 2) + rr * 8;
                const int t  = m >> 6;
                const int bq = m & 63;
                size_t base = (((((size_t)dir * LQ + t) * 8 + (bq >> 3)) * 8 + slc) * 8
                               + (bq & 7)) * 128 + gate * 32 + j;
                float2 v;
                v.x = acc[tm][tn][rr * 2 + 0] + b0;
                v.y = acc[tm][tn][rr * 2 + 1] + b1;
                *(float2*)&g_xw[base] = v;
            }
        }
    }
}

// ===========================================================================
// Kernel 2: recurrence via HMMA. Cluster of 8 CTAs per (dir, batch-group).
// 512 thr: warp w owns row-slab (w>>1) and k-half (w&1); W frags in regs.
// R14: DSMEM broadcast packed — lane groups of 4 pack hi/lo into 8-byte
// words via shuffles; only aj%4==0 lanes store => remote store REQUESTS drop
// 4096 -> 1024 per CTA-step (same bytes). out[] STG moved after the arrive.
// ===========================================================================
#define HPITCH 264   // halves per h row (8 batches x 256 k, padded: 528B rows)

__global__ void __cluster_dims__(8, 1, 1) __launch_bounds__(512, 1)
lstm_recurrence(const float* __restrict__ Whh_f,
                const float* __restrict__ Whh_b,
                const float* __restrict__ mask,
                float* __restrict__ out)
{
    __shared__ __align__(16) __nv_bfloat16 sh_hi[2][8][HPITCH];
    __shared__ __align__(16) __nv_bfloat16 sh_lo[2][8][HPITCH];
    __shared__ float gtp[2][8][132];

    const int tid  = threadIdx.x;
    const int lane = tid & 31;
    const int w    = tid >> 5;               // 0..15
    const int rs   = w >> 1;                 // row slab (16 rows)
    const int kh   = w & 1;                  // k half (128 k)
    const uint32_t s = ctarank();            // cluster rank = h-slice
    const int gid = blockIdx.x >> 3;         // 0..15
    const int dir = gid >> 3;                // 0 fwd, 1 bwd
    const int bg  = gid & 7;                 // batch group (8 batches)

    const float* Whh = dir ? Whh_b : Whh_f;

    // ---- load W_hh slice into mma A-fragments (split bf16 hi/lo), once ----
    const int r0 = 16 * rs + (lane >> 2);
    const int r1 = r0 + 8;
    const int grow0 = ((r0 >> 5) << 8) | ((int)s << 5) | (r0 & 31);
    const int grow1 = ((r1 >> 5) << 8) | ((int)s << 5) | (r1 & 31);
    const int kc = (lane & 3) * 2;

    uint32_t ahi[8][4], alo[8][4];
#pragma unroll
    for (int kt = 0; kt < 8; kt++) {
        const int kb = kh * 128 + kt * 16 + kc;
#pragma unroll
        for (int q = 0; q < 4; q++) {
            const int gr = (q & 1) ? grow1 : grow0;
            const int kk = kb + ((q >> 1) ? 8 : 0);
            float2 f = *(const float2*)&Whh[(size_t)gr * 256 + kk];
            float hx = __bfloat162float(__float2bfloat16(f.x));
            float hy = __bfloat162float(__float2bfloat16(f.y));
            ahi[kt][q] = pack_bf16(f.x, f.y);
            alo[kt][q] = pack_bf16(f.x - hx, f.y - hy);
        }
    }
    // Fragment reg order expected by mma: {(r0,k), (r1,k), (r0,k+8), (r1,k+8)}

    // zero phase-0 h buffers only (phase 1 is fully overwritten by stores)
    for (int idx = tid; idx < 8 * HPITCH; idx += 512) {
        sh_hi[0][0][idx] = __float2bfloat16(0.f);
        sh_lo[0][0][idx] = __float2bfloat16(0.f);
    }
    __syncthreads();

    // B-fragment ldmatrix addressing: rows = batch; this warp reads its k-half
    const uint32_t hbase  = smem_u32(&sh_hi[0][0][0]);
    const uint32_t lo_off = smem_u32(&sh_lo[0][0][0]) - hbase;
    const uint32_t ldm_off = (uint32_t)((lane & 7) * (HPITCH * 2)
                                        + (((lane >> 3) & 1) * 16)
                                        + kh * 256);   // k-half: 128 halves = 256B
    const uint32_t phase_sz = (uint32_t)(8 * HPITCH * 2);

    // activation role: threads 0..255, one (batch, h-index) each
    const int ab = (tid >> 5) & 7;
    const int aj = tid & 31;
    const int bglob_a = bg * 8 + ab;
    const int bcol = (lane & 3) * 2;

    // DSMEM group offset (local) for this lane-group's 4 packed h elements
    const uint32_t grp_hoff = (uint32_t)(ab * (HPITCH * 2)
                                         + ((int)s * 32 + (aj & ~3)) * 2);

    float c = 0.f;

    // base for (dir, bg, s); per-t stride = 65536 floats (validated R11)
    const float* xw_g = g_xw + ((size_t)dir * LQ * 64 + (size_t)bg * 8 + s) * 1024;

#pragma unroll 1
    for (int step = 0; step < LQ; step++) {
        const int t = dir ? (LQ - 1 - step) : step;
        const int p = step & 1;

        // ---- prefetch (independent of h) BEFORE the cluster wait;
        //      consumed only after syncthreads -> full-step latency cover ----
        const float* xwp = xw_g + (size_t)t * 65536;
        float xwv0 = 0.f, xwv1 = 0.f, xwv2 = 0.f, xwv3 = 0.f, m = 0.f;
        if (tid < 256) {
            xwv0 = xwp[ab * 128 +       aj];
            xwv1 = xwp[ab * 128 +  32 + aj];
            xwv2 = xwp[ab * 128 +  64 + aj];
            xwv3 = xwp[ab * 128 +  96 + aj];
            m    = __ldg(&mask[t * BQ + bglob_a]);
        }
        float accA[4] = {0.f, 0.f, 0.f, 0.f};
        float accB[4] = {0.f, 0.f, 0.f, 0.f};
        float accC[4] = {0.f, 0.f, 0.f, 0.f};

        if (step > 0)
            asm volatile("barrier.cluster.wait.aligned;" ::: "memory");

        // ---- matvec over this warp's k-half: 8 k-tiles, 3 indep chains ----
        const uint32_t hb = hbase + (uint32_t)p * phase_sz + ldm_off;
#pragma unroll
        for (int kt = 0; kt < 8; kt++) {
            uint32_t bh0, bh1, bl0, bl1;
            ldm_x2(bh0, bh1, hb + kt * 32);
            ldm_x2(bl0, bl1, hb + lo_off + kt * 32);
            mma_bf16(accA, ahi[kt], bh0, bh1);
            mma_bf16(accB, ahi[kt], bl0, bl1);
            mma_bf16(accC, alo[kt], bh0, bh1);
        }

        // ---- partial gates to smem (per k-half plane) ----
        gtp[kh][bcol][r0]     = accA[0] + accB[0] + accC[0];
        gtp[kh][bcol + 1][r0] = accA[1] + accB[1] + accC[1];
        gtp[kh][bcol][r1]     = accA[2] + accB[2] + accC[2];
        gtp[kh][bcol + 1][r1] = accA[3] + accB[3] + accC[3];
        __syncthreads();

        // ---- activations (threads 0..255) ----
        float hv = 0.f;
        unsigned short hhi = 0, hlo = 0;
        if (tid < 256) {
            float gi = gtp[0][ab][aj]      + gtp[1][ab][aj]      + xwv0;
            float gf = gtp[0][ab][32 + aj] + gtp[1][ab][32 + aj] + xwv1;
            float gg = gtp[0][ab][64 + aj] + gtp[1][ab][64 + aj] + xwv2;
            float go = gtp[0][ab][96 + aj] + gtp[1][ab][96 + aj] + xwv3;
            float i_ = sigm_e(gi);
            float f_ = sigm_e(gf);
            float g_ = tanh_e(gg);
            float o_ = sigm_e(go);
            c = f_ * c + i_ * g_;
            hv = o_ * tanh_e(c);
            hv *= m;
            c  *= m;

            hhi = __bfloat16_as_ushort(__float2bfloat16(hv));
            float hv_hi = __bfloat162float(__ushort_as_bfloat16(hhi));
            hlo = __bfloat16_as_ushort(__float2bfloat16(hv - hv_hi));
        }

        if (step < LQ - 1) {
            if (tid < 256) {
                // pack 4 lanes' hi and lo into 8B words (lane group leader)
                uint32_t vh = (uint32_t)hhi;
                uint32_t vl = (uint32_t)hlo;
                uint32_t h1 = __shfl_down_sync(0xFFFFFFFFu, vh, 1);
                uint32_t h2 = __shfl_down_sync(0xFFFFFFFFu, vh, 2);
                uint32_t h3 = __shfl_down_sync(0xFFFFFFFFu, vh, 3);
                uint32_t l1 = __shfl_down_sync(0xFFFFFFFFu, vl, 1);
                uint32_t l2 = __shfl_down_sync(0xFFFFFFFFu, vl, 2);
                uint32_t l3 = __shfl_down_sync(0xFFFFFFFFu, vl, 3);
                if ((aj & 3) == 0) {
                    uint64_t hq = (uint64_t)(vh | (h1 << 16))
                                | ((uint64_t)(h2 | (h3 << 16)) << 32);
                    uint64_t lq = (uint64_t)(vl | (l1 << 16))
                                | ((uint64_t)(l2 | (l3 << 16)) << 32);
                    uint32_t la = hbase + (uint32_t)(p ^ 1) * phase_sz + grp_hoff;
#pragma unroll
                    for (int rk = 0; rk < 8; rk++) {
                        uint32_t ra;
                        asm volatile("mapa.shared::cluster.u32 %0, %1, %2;"
                                     : "=r"(ra) : "r"(la), "r"(rk));
                        asm volatile("st.shared::cluster.b64 [%0], %1;"
                                     :: "r"(ra), "l"(hq) : "memory");
                        asm volatile("st.shared::cluster.b64 [%0], %1;"
                                     :: "r"(ra + lo_off), "l"(lq) : "memory");
                    }
                }
            }
            asm volatile("barrier.cluster.arrive.aligned;" ::: "memory");
        }

        // out[] store AFTER the broadcast/arrive — off the critical path
        if (tid < 256) {
            out[((size_t)t * BQ + bglob_a) * (2 * HALFQ) + dir * HALFQ
                + s * 32 + aj] = hv;
        }
    }
}

// ===========================================================================
// Launch
// Inputs (metadata order): x, mask, W_ih_f, W_hh_f, b_ih_f, b_hh_f,
//                          W_ih_b, W_hh_b, b_ih_b, b_hh_b
// Output: float32 (L, B, 2*HALF)
// ===========================================================================
extern "C" void kernel_launch(void* const* d_in, const int* in_sizes, int n_in,
                              void* d_out, int out_size)
{
    const float* x     = (const float*)d_in[0];
    const float* mask  = (const float*)d_in[1];
    const float* Wihf  = (const float*)d_in[2];
    const float* Whhf  = (const float*)d_in[3];
    const float* bihf  = (const float*)d_in[4];
    const float* bhhf  = (const float*)d_in[5];
    const float* Wihb  = (const float*)d_in[6];
    const float* Whhb  = (const float*)d_in[7];
    const float* bihb  = (const float*)d_in[8];
    const float* bhhb  = (const float*)d_in[9];
    float* out = (float*)d_out;

    // Phase 0: split-bf16 conversions + bias fold
    conv_x<<<16384, 256>>>(x);
    conv_w<<<1024, 256>>>(Wihf, Wihb, bihf, bhhf, bihb, bhhb);

    // Phase 1: tensor-core (HMMA) input projection into permuted scratch
    cudaFuncSetAttribute(lstm_gemm_mma,
                         cudaFuncAttributeMaxDynamicSharedMemorySize, GEMM_SMEM);
    dim3 ggrid(16, 256);   // n-tiles fast -> x tile reuse in L2
    lstm_gemm_mma<<<ggrid, 256, GEMM_SMEM>>>();

    // Phase 2: recurrence (128 CTAs x 512 thr, clusters of 8), packed DSMEM
    lstm_recurrence<<<128, 512>>>(Whhf, Whhb, mask, out);
}

// round 15
// speedup vs baseline: 3.0964x; 1.1503x over previous
#include <cuda_runtime.h>
#include <cuda_bf16.h>
#include <cstdint>
#include <cmath>

// Problem constants
#define LQ    512   // sequence length
#define BQ    64    // batch
#define DQ    512   // input dim
#define HALFQ 256   // hidden per direction
#define GATES 1024  // 4*HALF

// ---------------------------------------------------------------------------
// Scratch (layouts validated R8-R14)
// ---------------------------------------------------------------------------
__device__ __align__(16) float         g_xw[2ull * 512 * 8 * 8 * 8 * 128];
__device__ __align__(16) __nv_bfloat16 g_xhi[32768ull * 512];
__device__ __align__(16) __nv_bfloat16 g_xlo[32768ull * 512];
__device__ __align__(16) __nv_bfloat16 g_whi[2048ull * 512];
__device__ __align__(16) __nv_bfloat16 g_wlo[2048ull * 512];
__device__ __align__(16) float         g_bsum[2048];

// ---------------------------------------------------------------------------
// Helpers
// ---------------------------------------------------------------------------
__device__ __forceinline__ uint32_t smem_u32(const void* p) {
    uint32_t a;
    asm("{ .reg .u64 t; cvta.to.shared.u64 t, %1; cvt.u32.u64 %0, t; }"
        : "=r"(a) : "l"(p));
    return a;
}
__device__ __forceinline__ uint32_t ctarank() {
    uint32_t r;
    asm("mov.u32 %0, %%cluster_ctarank;" : "=r"(r));
    return r;
}
__device__ __forceinline__ void cp16(uint32_t dst, const void* src) {
    asm volatile("cp.async.cg.shared.global [%0], [%1], 16;"
                 :: "r"(dst), "l"(src) : "memory");
}
__device__ __forceinline__ void cp_commit() {
    asm volatile("cp.async.commit_group;" ::: "memory");
}
template <int N>
__device__ __forceinline__ void cp_wait() {
    asm volatile("cp.async.wait_group %0;" :: "n"(N) : "memory");
}
__device__ __forceinline__ void ldm_x4(uint32_t& r0, uint32_t& r1,
                                       uint32_t& r2, uint32_t& r3, uint32_t a) {
    asm volatile("ldmatrix.sync.aligned.m8n8.x4.shared.b16 {%0,%1,%2,%3}, [%4];"
                 : "=r"(r0), "=r"(r1), "=r"(r2), "=r"(r3) : "r"(a));
}
__device__ __forceinline__ void mma_bf16(float* c, const uint32_t* a,
                                         uint32_t b0, uint32_t b1) {
    asm volatile("mma.sync.aligned.m16n8k16.row.col.f32.bf16.bf16.f32 "
                 "{%0,%1,%2,%3}, {%4,%5,%6,%7}, {%8,%9}, {%0,%1,%2,%3};"
                 : "+f"(c[0]), "+f"(c[1]), "+f"(c[2]), "+f"(c[3])
                 : "r"(a[0]), "r"(a[1]), "r"(a[2]), "r"(a[3]),
                   "r"(b0), "r"(b1));
}
// accurate activations via MUFU exp (error ~1e-6; validated R8/R11-R14)
__device__ __forceinline__ float sigm_e(float x) {
    return __fdividef(1.f, 1.f + __expf(-x));
}
__device__ __forceinline__ float tanh_e(float x) {
    return 1.f - __fdividef(2.f, __expf(2.f * x) + 1.f);
}
__device__ __forceinline__ uint32_t pack_bf16(float a, float b) {
    return (uint32_t)__bfloat16_as_ushort(__float2bfloat16(a)) |
           ((uint32_t)__bfloat16_as_ushort(__float2bfloat16(b)) << 16);
}

// ===========================================================================
// Kernel 0a: split x into hi/lo bf16
// ===========================================================================
__global__ __launch_bounds__(256)
void conv_x(const float* __restrict__ x)
{
    size_t i = ((size_t)blockIdx.x * 256 + threadIdx.x) * 4;
    float4 v = *(const float4*)(x + i);
    float vv[4] = {v.x, v.y, v.z, v.w};
    unsigned short hi[4], lo[4];
#pragma unroll
    for (int j = 0; j < 4; j++) {
        __nv_bfloat16 h = __float2bfloat16(vv[j]);
        __nv_bfloat16 l = __float2bfloat16(vv[j] - __bfloat162float(h));
        hi[j] = __bfloat16_as_ushort(h);
        lo[j] = __bfloat16_as_ushort(l);
    }
    *(uint2*)((unsigned short*)g_xhi + i) = *(uint2*)hi;
    *(uint2*)((unsigned short*)g_xlo + i) = *(uint2*)lo;
}

// ===========================================================================
// Kernel 0b: split W into hi/lo bf16 (concat fwd|bwd), and combined biases
// ===========================================================================
__global__ __launch_bounds__(256)
void conv_w(const float* __restrict__ Wf, const float* __restrict__ Wb,
            const float* __restrict__ bihf, const float* __restrict__ bhhf,
            const float* __restrict__ bihb, const float* __restrict__ bhhb)
{
    size_t e0 = ((size_t)blockIdx.x * 256 + threadIdx.x) * 4;
    int row = (int)(e0 >> 9);
    int col = (int)(e0 & 511);
    const float* src = (row < GATES) ? (Wf + (size_t)row * 512 + col)
                                     : (Wb + (size_t)(row - GATES) * 512 + col);
    float4 v = *(const float4*)src;
    float vv[4] = {v.x, v.y, v.z, v.w};
    unsigned short hi[4], lo[4];
#pragma unroll
    for (int j = 0; j < 4; j++) {
        __nv_bfloat16 h = __float2bfloat16(vv[j]);
        __nv_bfloat16 l = __float2bfloat16(vv[j] - __bfloat162float(h));
        hi[j] = __bfloat16_as_ushort(h);
        lo[j] = __bfloat16_as_ushort(l);
    }
    *(uint2*)((unsigned short*)g_whi + e0) = *(uint2*)hi;
    *(uint2*)((unsigned short*)g_wlo + e0) = *(uint2*)lo;

    if (blockIdx.x == 0) {
        for (int n = threadIdx.x; n < 2048; n += 256) {
            int r = n & (GATES - 1);
            g_bsum[n] = (n < GATES) ? (bihf[r] + bhhf[r]) : (bihb[r] + bhhb[r]);
        }
    }
}

// ===========================================================================
// Kernel 1: mma.sync bf16 GEMM  C[32768,2048] = x @ Wcat^T + bsum
// (unchanged — validated R8/R11-R14, rel_err 6e-6)
// ===========================================================================
#define STG_HALF 20480                      // halves per stage (4 * 128*40)
#define GEMM_SMEM (3 * STG_HALF * 2)        // 122880 bytes

__device__ __forceinline__ void stage_load(uint32_t smbase, int st,
                                           int m0, int n0, int k0, int tid)
{
    const __nv_bfloat16* const xh = g_xhi + (size_t)m0 * 512 + k0;
    const __nv_bfloat16* const xl = g_xlo + (size_t)m0 * 512 + k0;
    const __nv_bfloat16* const wh = g_whi + (size_t)n0 * 512 + k0;
    const __nv_bfloat16* const wl = g_wlo + (size_t)n0 * 512 + k0;
    const uint32_t sbase = smbase + st * (STG_HALF * 2);
    const int r0  = tid >> 2;          // 0..63
    const int seg = tid & 3;           // 0..3

#pragma unroll
    for (int mat = 0; mat < 4; mat++) {
        const __nv_bfloat16* src =
            (mat == 0) ? xh : (mat == 1) ? xl : (mat == 2) ? wh : wl;
#pragma unroll
        for (int hh = 0; hh < 2; hh++) {
            int row = r0 + hh * 64;
            uint32_t dst = sbase + (uint32_t)(mat * 10240 + row * 80 + seg * 16);
            cp16(dst, src + (size_t)row * 512 + seg * 8);
        }
    }
}

__global__ __launch_bounds__(256)
void lstm_gemm_mma()
{
    extern __shared__ char smg[];
    const uint32_t smbase = smem_u32(smg);
    const int tid  = threadIdx.x;
    const int lane = tid & 31;
    const int wid  = tid >> 5;
    const int wm = (wid & 3) * 32;          // warp m offset
    const int wn = (wid >> 2) * 64;         // warp n offset
    const int n0 = blockIdx.x * 128;        // 16 n-tiles (fast -> x reuse in L2)
    const int m0 = blockIdx.y * 128;        // 256 m-tiles

    float acc[2][8][4];
#pragma unroll
    for (int i = 0; i < 2; i++)
#pragma unroll
        for (int j = 0; j < 8; j++)
#pragma unroll
            for (int q = 0; q < 4; q++) acc[i][j][q] = 0.f;

    const uint32_t a_row = (uint32_t)(lane & 15);
    const uint32_t a_col = (uint32_t)((lane >> 4) * 8);
    const uint32_t b_row = (uint32_t)((lane & 7) + ((lane >> 4) << 3));
    const uint32_t b_col = (uint32_t)(((lane >> 3) & 1) * 8);

    stage_load(smbase, 0, m0, n0, 0, tid);  cp_commit();
    stage_load(smbase, 1, m0, n0, 32, tid); cp_commit();

    for (int c = 0; c < 16; c++) {
        if (c + 2 < 16) stage_load(smbase, (c + 2) % 3, m0, n0, (c + 2) * 32, tid);
        cp_commit();
        cp_wait<2>();
        __syncthreads();

        uint32_t sb  = smbase + (uint32_t)((c % 3) * (STG_HALF * 2));
        uint32_t sAh = sb;
        uint32_t sAl = sb + 10240;
        uint32_t sBh = sb + 20480;
        uint32_t sBl = sb + 30720;

#pragma unroll
        for (int kk = 0; kk < 2; kk++) {
            const uint32_t kb = (uint32_t)(kk * 32);

            uint32_t ah[2][4], al[2][4];
#pragma unroll
            for (int tm = 0; tm < 2; tm++) {
                uint32_t roff = (uint32_t)(wm + tm * 16) + a_row;
                uint32_t off = roff * 80 + kb + a_col * 2;
                ldm_x4(ah[tm][0], ah[tm][1], ah[tm][2], ah[tm][3], sAh + off);
                ldm_x4(al[tm][0], al[tm][1], al[tm][2], al[tm][3], sAl + off);
            }

            uint32_t b[16];
#pragma unroll
            for (int p = 0; p < 4; p++) {
                uint32_t roff = (uint32_t)(wn + p * 16) + b_row;
                uint32_t off = roff * 80 + kb + b_col * 2;
                ldm_x4(b[p * 4 + 0], b[p * 4 + 1], b[p * 4 + 2], b[p * 4 + 3],
                       sBh + off);
            }
#pragma unroll
            for (int tm = 0; tm < 2; tm++)
#pragma unroll
                for (int tn = 0; tn < 8; tn++) {
                    mma_bf16(acc[tm][tn], ah[tm], b[tn * 2], b[tn * 2 + 1]);
                    mma_bf16(acc[tm][tn], al[tm], b[tn * 2], b[tn * 2 + 1]);
                }
#pragma unroll
            for (int p = 0; p < 4; p++) {
                uint32_t roff = (uint32_t)(wn + p * 16) + b_row;
                uint32_t off = roff * 80 + kb + b_col * 2;
                ldm_x4(b[p * 4 + 0], b[p * 4 + 1], b[p * 4 + 2], b[p * 4 + 3],
                       sBl + off);
            }
#pragma unroll
            for (int tm = 0; tm < 2; tm++)
#pragma unroll
                for (int tn = 0; tn < 8; tn++)
                    mma_bf16(acc[tm][tn], ah[tm], b[tn * 2], b[tn * 2 + 1]);
        }
        __syncthreads();
    }

#pragma unroll
    for (int tm = 0; tm < 2; tm++) {
#pragma unroll
        for (int tn = 0; tn < 8; tn++) {
            const int n    = n0 + wn + tn * 8 + (lane & 3) * 2;
            const int dir  = n >> 10;
            const int rowg = n & (GATES - 1);
            const int gate = rowg >> 8;
            const int slc  = (rowg >> 5) & 7;
            const int j    = rowg & 31;
            float b0 = g_bsum[n];
            float b1 = g_bsum[n + 1];
#pragma unroll
            for (int rr = 0; rr < 2; rr++) {
                const int m  = m0 + wm + tm * 16 + (lane >> 2) + rr * 8;
                const int t  = m >> 6;
                const int bq = m & 63;
                size_t base = (((((size_t)dir * LQ + t) * 8 + (bq >> 3)) * 8 + slc) * 8
                               + (bq & 7)) * 128 + gate * 32 + j;
                float2 v;
                v.x = acc[tm][tn][rr * 2 + 0] + b0;
                v.y = acc[tm][tn][rr * 2 + 1] + b1;
                *(float2*)&g_xw[base] = v;
            }
        }
    }
}

// ===========================================================================
// Kernel 2: recurrence via HMMA. Cluster of 8 CTAs.
// R15: each cluster runs TWO batch-groups (16 batches) per step under ONE
// cluster barrier — the fixed sync latency (barrier + DSMEM drain + skew,
// shown by R12-R14 to dominate) is amortized over 2 chains. 64 CTAs x 512thr.
// xW prefetch now staged through smem via cp.async (double-buffered) to free
// registers and fully hide the LDG latency.
// ===========================================================================
#define HPITCH   264                         // halves per h row (pad: 528B)
#define R_SH_HI  0                           // [2][16][HPITCH] bf16
#define R_SH_LO  16896                       // [2][16][HPITCH] bf16
#define R_GTP    33792                       // [2][16][132] float
#define R_XWS    50688                       // [2][2048] float
#define REC_SMEM 67072

__global__ void __cluster_dims__(8, 1, 1) __launch_bounds__(512, 1)
lstm_recurrence(const float* __restrict__ Whh_f,
                const float* __restrict__ Whh_b,
                const float* __restrict__ mask,
                float* __restrict__ out)
{
    extern __shared__ char smr[];
    float* gtp = (float*)(smr + R_GTP);      // [(kh*16+b)*132 + r]
    float* xws = (float*)(smr + R_XWS);      // [p*2048 + ab*128 + g*32 + j]

    const int tid  = threadIdx.x;
    const int lane = tid & 31;
    const int w    = tid >> 5;               // 0..15
    const int rs   = w >> 1;                 // row slab (16 rows of 128)
    const int kh   = w & 1;                  // k half (128 of 256)
    const uint32_t s = ctarank();            // cluster rank = h-slice
    const int gid = blockIdx.x >> 3;         // 0..7
    const int dir = gid >> 2;                // 0 fwd, 1 bwd
    const int bgp = gid & 3;                 // batch-group PAIR (16 batches)

    const float* Whh = dir ? Whh_b : Whh_f;

    // ---- load W_hh slice into mma A-fragments (split bf16 hi/lo), once ----
    const int r0 = 16 * rs + (lane >> 2);
    const int r1 = r0 + 8;
    const int grow0 = ((r0 >> 5) << 8) | ((int)s << 5) | (r0 & 31);
    const int grow1 = ((r1 >> 5) << 8) | ((int)s << 5) | (r1 & 31);
    const int kc = (lane & 3) * 2;

    uint32_t ahi[8][4], alo[8][4];
#pragma unroll
    for (int kt = 0; kt < 8; kt++) {
        const int kb = kh * 128 + kt * 16 + kc;
#pragma unroll
        for (int q = 0; q < 4; q++) {
            const int gr = (q & 1) ? grow1 : grow0;
            const int kk = kb + ((q >> 1) ? 8 : 0);
            float2 f = *(const float2*)&Whh[(size_t)gr * 256 + kk];
            float hx = __bfloat162float(__float2bfloat16(f.x));
            float hy = __bfloat162float(__float2bfloat16(f.y));
            ahi[kt][q] = pack_bf16(f.x, f.y);
            alo[kt][q] = pack_bf16(f.x - hx, f.y - hy);
        }
    }

    // zero phase-0 h buffers (both planes); phase 1 fully overwritten later
    {
        __nv_bfloat16* zh = (__nv_bfloat16*)(smr + R_SH_HI);
        __nv_bfloat16* zl = (__nv_bfloat16*)(smr + R_SH_LO);
        for (int idx = tid; idx < 16 * HPITCH; idx += 512) {
            zh[idx] = __float2bfloat16(0.f);
            zl[idx] = __float2bfloat16(0.f);
        }
    }
    __syncthreads();

    const uint32_t hbase  = smem_u32(smr) + R_SH_HI;
    const uint32_t lo_off = R_SH_LO - R_SH_HI;
    // B-fragment (n=16) ldmatrix addressing — same pattern as the validated GEMM
    const uint32_t b_row  = (uint32_t)((lane & 7) + ((lane >> 4) << 3));
    const uint32_t ldm_off = b_row * (HPITCH * 2)
                           + (((lane >> 3) & 1) * 16)
                           + (uint32_t)kh * 256;
    const uint32_t phase_sz = (uint32_t)(16 * HPITCH * 2);

    // activation role: ALL 512 threads, one (batch, h-index) each
    const int ab = w;                        // batch within pair-group (0..15)
    const int aj = lane;
    const int bglob_a = bgp * 16 + ab;
    const int bcol = (lane & 3) * 2;

    // cp.async role: thread (ab, g=lane>>3, grp=lane&7) fetches 16B of xW
    const int cg  = lane >> 3;               // gate 0..3
    const int cgr = lane & 7;                // 4-float group
    const float* xw_src_base = g_xw
        + ((size_t)dir * LQ * 64 + (size_t)(bgp * 2 + (ab >> 3)) * 8 + s) * 1024
        + (size_t)(ab & 7) * 128 + cg * 32 + cgr * 4;
    const uint32_t xw_dst_base = smem_u32(smr) + R_XWS
        + (uint32_t)(ab * 128 + cg * 32 + cgr * 4) * 4;

    // DSMEM group offset for this lane-group's 4 packed h elements
    const uint32_t grp_hoff = (uint32_t)(ab * (HPITCH * 2)
                                         + ((int)s * 32 + (aj & ~3)) * 2);

    float c = 0.f;

#pragma unroll 1
    for (int step = 0; step < LQ; step++) {
        const int t = dir ? (LQ - 1 - step) : step;
        const int p = step & 1;

        // ---- prefetch xW into smem stage + mask (before the cluster wait) --
        cp16(xw_dst_base + (uint32_t)p * 8192, xw_src_base + (size_t)t * 65536);
        cp_commit();
        float m = __ldg(&mask[t * BQ + bglob_a]);

        if (step > 0)
            asm volatile("barrier.cluster.wait.aligned;" ::: "memory");

        // ---- matvec: this warp's k-half, n=16 (two 8-batch tiles) ----
        float acc0[4] = {0.f, 0.f, 0.f, 0.f};
        float acc1[4] = {0.f, 0.f, 0.f, 0.f};
        const uint32_t hb = hbase + (uint32_t)p * phase_sz + ldm_off;
#pragma unroll
        for (int kt = 0; kt < 8; kt++) {
            uint32_t bh0, bh1, bh2, bh3, bl0, bl1, bl2, bl3;
            ldm_x4(bh0, bh1, bh2, bh3, hb + kt * 32);
            ldm_x4(bl0, bl1, bl2, bl3, hb + lo_off + kt * 32);
            mma_bf16(acc0, ahi[kt], bh0, bh1);
            mma_bf16(acc1, ahi[kt], bh2, bh3);
            mma_bf16(acc0, ahi[kt], bl0, bl1);
            mma_bf16(acc1, ahi[kt], bl2, bl3);
            mma_bf16(acc0, alo[kt], bh0, bh1);
            mma_bf16(acc1, alo[kt], bh2, bh3);
        }

        // ---- partial gates to smem (per k-half plane, 16 batches) ----
        gtp[(kh * 16 + bcol)     * 132 + r0] = acc0[0];
        gtp[(kh * 16 + bcol + 1) * 132 + r0] = acc0[1];
        gtp[(kh * 16 + bcol)     * 132 + r1] = acc0[2];
        gtp[(kh * 16 + bcol + 1) * 132 + r1] = acc0[3];
        gtp[(kh * 16 + 8 + bcol)     * 132 + r0] = acc1[0];
        gtp[(kh * 16 + 8 + bcol + 1) * 132 + r0] = acc1[1];
        gtp[(kh * 16 + 8 + bcol)     * 132 + r1] = acc1[2];
        gtp[(kh * 16 + 8 + bcol + 1) * 132 + r1] = acc1[3];
        cp_wait<0>();
        __syncthreads();

        // ---- activations (all 512 threads) ----
        const float* xwp = xws + p * 2048 + ab * 128;
        float gi = gtp[ab * 132 + aj]      + gtp[(16 + ab) * 132 + aj]      + xwp[aj];
        float gf = gtp[ab * 132 + 32 + aj] + gtp[(16 + ab) * 132 + 32 + aj] + xwp[32 + aj];
        float gg = gtp[ab * 132 + 64 + aj] + gtp[(16 + ab) * 132 + 64 + aj] + xwp[64 + aj];
        float go = gtp[ab * 132 + 96 + aj] + gtp[(16 + ab) * 132 + 96 + aj] + xwp[96 + aj];
        float i_ = sigm_e(gi);
        float f_ = sigm_e(gf);
        float g_ = tanh_e(gg);
        float o_ = sigm_e(go);
        c = f_ * c + i_ * g_;
        float hv = o_ * tanh_e(c);
        hv *= m;
        c  *= m;

        unsigned short hhi = __bfloat16_as_ushort(__float2bfloat16(hv));
        float hv_hi = __bfloat162float(__ushort_as_bfloat16(hhi));
        unsigned short hlo = __bfloat16_as_ushort(__float2bfloat16(hv - hv_hi));

        if (step < LQ - 1) {
            // pack 4 lanes' hi/lo into 8B words; leaders store to 8 ranks
            uint32_t vh = (uint32_t)hhi;
            uint32_t vl = (uint32_t)hlo;
            uint32_t h1 = __shfl_down_sync(0xFFFFFFFFu, vh, 1);
            uint32_t h2 = __shfl_down_sync(0xFFFFFFFFu, vh, 2);
            uint32_t h3 = __shfl_down_sync(0xFFFFFFFFu, vh, 3);
            uint32_t l1 = __shfl_down_sync(0xFFFFFFFFu, vl, 1);
            uint32_t l2 = __shfl_down_sync(0xFFFFFFFFu, vl, 2);
            uint32_t l3 = __shfl_down_sync(0xFFFFFFFFu, vl, 3);
            if ((aj & 3) == 0) {
                uint64_t hq = (uint64_t)(vh | (h1 << 16))
                            | ((uint64_t)(h2 | (h3 << 16)) << 32);
                uint64_t lq = (uint64_t)(vl | (l1 << 16))
                            | ((uint64_t)(l2 | (l3 << 16)) << 32);
                uint32_t la = hbase + (uint32_t)(p ^ 1) * phase_sz + grp_hoff;
#pragma unroll
                for (int rk = 0; rk < 8; rk++) {
                    uint32_t ra;
                    asm volatile("mapa.shared::cluster.u32 %0, %1, %2;"
                                 : "=r"(ra) : "r"(la), "r"(rk));
                    asm volatile("st.shared::cluster.b64 [%0], %1;"
                                 :: "r"(ra), "l"(hq) : "memory");
                    asm volatile("st.shared::cluster.b64 [%0], %1;"
                                 :: "r"(ra + lo_off), "l"(lq) : "memory");
                }
            }
            asm volatile("barrier.cluster.arrive.aligned;" ::: "memory");
        }

        // out[] store AFTER the broadcast/arrive — off the critical path
        out[((size_t)t * BQ + bglob_a) * (2 * HALFQ) + dir * HALFQ
            + s * 32 + aj] = hv;
    }
}

// ===========================================================================
// Launch
// Inputs (metadata order): x, mask, W_ih_f, W_hh_f, b_ih_f, b_hh_f,
//                          W_ih_b, W_hh_b, b_ih_b, b_hh_b
// Output: float32 (L, B, 2*HALF)
// ===========================================================================
extern "C" void kernel_launch(void* const* d_in, const int* in_sizes, int n_in,
                              void* d_out, int out_size)
{
    const float* x     = (const float*)d_in[0];
    const float* mask  = (const float*)d_in[1];
    const float* Wihf  = (const float*)d_in[2];
    const float* Whhf  = (const float*)d_in[3];
    const float* bihf  = (const float*)d_in[4];
    const float* bhhf  = (const float*)d_in[5];
    const float* Wihb  = (const float*)d_in[6];
    const float* Whhb  = (const float*)d_in[7];
    const float* bihb  = (const float*)d_in[8];
    const float* bhhb  = (const float*)d_in[9];
    float* out = (float*)d_out;

    // Phase 0: split-bf16 conversions + bias fold
    conv_x<<<16384, 256>>>(x);
    conv_w<<<1024, 256>>>(Wihf, Wihb, bihf, bhhf, bihb, bhhb);

    // Phase 1: tensor-core (HMMA) input projection into permuted scratch
    cudaFuncSetAttribute(lstm_gemm_mma,
                         cudaFuncAttributeMaxDynamicSharedMemorySize, GEMM_SMEM);
    dim3 ggrid(16, 256);   // n-tiles fast -> x tile reuse in L2
    lstm_gemm_mma<<<ggrid, 256, GEMM_SMEM>>>();

    // Phase 2: recurrence — 64 CTAs x 512 thr, 8 clusters, 2 chains/cluster
    cudaFuncSetAttribute(lstm_recurrence,
                         cudaFuncAttributeMaxDynamicSharedMemorySize, REC_SMEM);
    lstm_recurrence<<<64, 512, REC_SMEM>>>(Whhf, Whhb, mask, out);
}